// round 1
// baseline (speedup 1.0000x reference)
#include <cuda_runtime.h>
#include <math.h>

// Problem constants
#define T_SEQ   2048
#define B_SZ    2
#define E_DIM   2048
#define H_Q     16
#define H_KV    4
#define D_HEAD  128
#define M_ROWS  4096        // B*T
#define WIN     512

// ---------------------------------------------------------------------------
// Scratch (device globals: allocation-free rule)
// ---------------------------------------------------------------------------
__device__ float g_q  [M_ROWS * (H_Q  * D_HEAD)];   // 32 MB
__device__ float g_k  [M_ROWS * (H_KV * D_HEAD)];   // 8 MB
__device__ float g_v  [M_ROWS * (H_KV * D_HEAD)];   // 8 MB
__device__ float g_att[M_ROWS * (H_Q  * D_HEAD)];   // 32 MB
__device__ float g_cos[T_SEQ * 64];
__device__ float g_sin[T_SEQ * 64];

// ---------------------------------------------------------------------------
// RoPE table: mimic JAX fp32 inv_freq / angle rounding, accurate trig
// ---------------------------------------------------------------------------
__global__ void rope_table_kernel() {
    int idx = blockIdx.x * 256 + threadIdx.x;          // T_SEQ*64 = 131072
    if (idx >= T_SEQ * 64) return;
    int i = idx & 63;
    int t = idx >> 6;
    float ex = (float)(2 * i) * (1.0f / 128.0f);       // exact in fp32
    float invf = (float)(1.0 / pow(10000.0, (double)ex));  // correctly-rounded fp32
    float ang = (float)t * invf;                       // fp32 angle, as in reference
    double s, c;
    sincos((double)ang, &s, &c);
    g_cos[idx] = (float)c;
    g_sin[idx] = (float)s;
}

// ---------------------------------------------------------------------------
// RoPE apply: buf is [M_ROWS][heads][128]; rotate halves (0..63 | 64..127)
// ---------------------------------------------------------------------------
__global__ void rope_apply_kernel(float* __restrict__ buf, int heads, int hshift) {
    int idx = blockIdx.x * 256 + threadIdx.x;
    int total = M_ROWS * heads * 64;
    if (idx >= total) return;
    int i = idx & 63;
    int h = (idx >> 6) & (heads - 1);
    int m = idx >> (6 + hshift);
    int t = m & (T_SEQ - 1);
    float c = g_cos[t * 64 + i];
    float s = g_sin[t * 64 + i];
    float* p = buf + ((size_t)m * heads + h) * D_HEAD + i;
    float x1 = p[0];
    float x2 = p[64];
    p[0]  = x1 * c - x2 * s;
    p[64] = x2 * c + x1 * s;
}

// ---------------------------------------------------------------------------
// SGEMM (NT): C[M,N] = A[M,K] * B[N,K]^T, fp32, M%128==0, N%128==0, K%16==0
// 128x128 block tile, BK=16, 256 threads, 8x8 per-thread micro-tile.
// ---------------------------------------------------------------------------
__global__ void __launch_bounds__(256) sgemm_nt(
    const float* __restrict__ A, const float* __restrict__ B,
    float* __restrict__ C, int M, int N, int K)
{
    __shared__ float As[16][128];
    __shared__ float Bs[16][128];

    const int tid = threadIdx.x;
    const int bm = blockIdx.y * 128;
    const int bn = blockIdx.x * 128;
    const int tx = tid & 15;      // output col group
    const int ty = tid >> 4;      // output row group

    // load mapping: 2 float4 per array per thread
    const int lr0 = tid >> 2;                // 0..63
    const int lk0 = (tid & 3) << 2;          // 0,4,8,12
    const int lr1 = lr0 + 64;

    const float* Ap0 = A + (size_t)(bm + lr0) * K + lk0;
    const float* Ap1 = A + (size_t)(bm + lr1) * K + lk0;
    const float* Bp0 = B + (size_t)(bn + lr0) * K + lk0;
    const float* Bp1 = B + (size_t)(bn + lr1) * K + lk0;

    float acc[8][8];
    #pragma unroll
    for (int i = 0; i < 8; i++)
        #pragma unroll
        for (int j = 0; j < 8; j++) acc[i][j] = 0.0f;

    for (int k0 = 0; k0 < K; k0 += 16) {
        float4 a0 = *(const float4*)(Ap0 + k0);
        float4 a1 = *(const float4*)(Ap1 + k0);
        float4 b0 = *(const float4*)(Bp0 + k0);
        float4 b1 = *(const float4*)(Bp1 + k0);
        __syncthreads();
        As[lk0 + 0][lr0] = a0.x; As[lk0 + 1][lr0] = a0.y;
        As[lk0 + 2][lr0] = a0.z; As[lk0 + 3][lr0] = a0.w;
        As[lk0 + 0][lr1] = a1.x; As[lk0 + 1][lr1] = a1.y;
        As[lk0 + 2][lr1] = a1.z; As[lk0 + 3][lr1] = a1.w;
        Bs[lk0 + 0][lr0] = b0.x; Bs[lk0 + 1][lr0] = b0.y;
        Bs[lk0 + 2][lr0] = b0.z; Bs[lk0 + 3][lr0] = b0.w;
        Bs[lk0 + 0][lr1] = b1.x; Bs[lk0 + 1][lr1] = b1.y;
        Bs[lk0 + 2][lr1] = b1.z; Bs[lk0 + 3][lr1] = b1.w;
        __syncthreads();
        #pragma unroll
        for (int kk = 0; kk < 16; kk++) {
            float ra[8], rb[8];
            *(float4*)(ra)     = *(const float4*)&As[kk][ty * 8];
            *(float4*)(ra + 4) = *(const float4*)&As[kk][ty * 8 + 4];
            *(float4*)(rb)     = *(const float4*)&Bs[kk][tx * 8];
            *(float4*)(rb + 4) = *(const float4*)&Bs[kk][tx * 8 + 4];
            #pragma unroll
            for (int i = 0; i < 8; i++)
                #pragma unroll
                for (int j = 0; j < 8; j++)
                    acc[i][j] += ra[i] * rb[j];
        }
    }

    #pragma unroll
    for (int i = 0; i < 8; i++) {
        float* crow = C + (size_t)(bm + ty * 8 + i) * N + bn + tx * 8;
        *(float4*)(crow)     = make_float4(acc[i][0], acc[i][1], acc[i][2], acc[i][3]);
        *(float4*)(crow + 4) = make_float4(acc[i][4], acc[i][5], acc[i][6], acc[i][7]);
    }
}

// ---------------------------------------------------------------------------
// Attention: 1 CTA = (64 queries, head h, batch b). Sliding-window causal GQA.
// 128 threads. Online softmax, O in registers.
// ---------------------------------------------------------------------------
struct AttnSmem {
    float Qt[128][64];     // Q transposed: [d][row]
    float Kt[128][64];     // K transposed: [d][col]
    float Vs[64][128];     // V row-major:  [col][d]
    float Ss[64][65];      // scores / probs (padded)
    float mrow[64];
    float lrow[64];
    float crow[64];
};

__global__ void __launch_bounds__(128) attn_kernel(
    const float* __restrict__ q, const float* __restrict__ k,
    const float* __restrict__ v, float* __restrict__ o)
{
    extern __shared__ char smem_raw[];
    AttnSmem& sm = *reinterpret_cast<AttnSmem*>(smem_raw);

    const int tid = threadIdx.x;
    const int qs  = blockIdx.x * 64;
    const int h   = blockIdx.y;
    const int b   = blockIdx.z;
    const int kvh = h >> 2;                      // N_REP = 4
    const float scale = 0.08838834764831845f;    // 1/sqrt(128)

    // ---- load Q tile (transposed into smem) ----
    {
        int r  = tid >> 1;
        int dh = (tid & 1) * 64;
        const float* src = q + ((size_t)(b * T_SEQ + qs + r) * H_Q + h) * D_HEAD + dh;
        #pragma unroll
        for (int j = 0; j < 16; j++) {
            float4 t4 = *(const float4*)(src + j * 4);
            sm.Qt[dh + j * 4 + 0][r] = t4.x;
            sm.Qt[dh + j * 4 + 1][r] = t4.y;
            sm.Qt[dh + j * 4 + 2][r] = t4.z;
            sm.Qt[dh + j * 4 + 3][r] = t4.w;
        }
    }
    if (tid < 64) { sm.mrow[tid] = -1e30f; sm.lrow[tid] = 0.0f; }

    const int tq = tid & 15;     // S phase: rows tq*4..+3
    const int tk = tid >> 4;     // S phase: cols tk*8..+7
    const int tr = tid & 15;     // PV phase: rows tr*4..+3
    const int td = tid >> 4;     // PV phase: cols td*16..+15

    float Oacc[4][16];
    #pragma unroll
    for (int i = 0; i < 4; i++)
        #pragma unroll
        for (int j = 0; j < 16; j++) Oacc[i][j] = 0.0f;

    int kb0 = qs - WIN; if (kb0 < 0) kb0 = 0;

    for (int kb = kb0; kb <= qs; kb += 64) {
        __syncthreads();   // protect Kt/Vs (+ initial mrow/lrow/Qt visibility)

        // ---- load K (transposed) and V ----
        {
            int r  = tid >> 1;
            int dh = (tid & 1) * 64;
            const float* ksrc = k + ((size_t)(b * T_SEQ + kb + r) * H_KV + kvh) * D_HEAD + dh;
            const float* vsrc = v + ((size_t)(b * T_SEQ + kb + r) * H_KV + kvh) * D_HEAD + dh;
            #pragma unroll
            for (int j = 0; j < 16; j++) {
                float4 t4 = *(const float4*)(ksrc + j * 4);
                sm.Kt[dh + j * 4 + 0][r] = t4.x;
                sm.Kt[dh + j * 4 + 1][r] = t4.y;
                sm.Kt[dh + j * 4 + 2][r] = t4.z;
                sm.Kt[dh + j * 4 + 3][r] = t4.w;
            }
            #pragma unroll
            for (int j = 0; j < 16; j++) {
                *(float4*)&sm.Vs[r][dh + j * 4] = *(const float4*)(vsrc + j * 4);
            }
        }
        __syncthreads();

        // ---- S = (Q K^T) ----
        float sacc[4][8];
        #pragma unroll
        for (int i = 0; i < 4; i++)
            #pragma unroll
            for (int j = 0; j < 8; j++) sacc[i][j] = 0.0f;

        #pragma unroll 4
        for (int d = 0; d < 128; d++) {
            float ra[4], rb[8];
            *(float4*)(ra)     = *(const float4*)&sm.Qt[d][tq * 4];
            *(float4*)(rb)     = *(const float4*)&sm.Kt[d][tk * 8];
            *(float4*)(rb + 4) = *(const float4*)&sm.Kt[d][tk * 8 + 4];
            #pragma unroll
            for (int i = 0; i < 4; i++)
                #pragma unroll
                for (int j = 0; j < 8; j++)
                    sacc[i][j] += ra[i] * rb[j];
        }

        // ---- mask + scale, write to smem ----
        #pragma unroll
        for (int i = 0; i < 4; i++) {
            int qr = qs + tq * 4 + i;
            #pragma unroll
            for (int j = 0; j < 8; j++) {
                int kc = kb + tk * 8 + j;
                bool valid = (kc <= qr) && (qr - kc < WIN);
                sm.Ss[tq * 4 + i][tk * 8 + j] = valid ? sacc[i][j] * scale : -1e30f;
            }
        }
        __syncthreads();

        // ---- online softmax row pass ----
        if (tid < 64) {
            int r = tid;
            float mo = sm.mrow[r];
            float mx = mo;
            #pragma unroll 8
            for (int c = 0; c < 64; c++) mx = fmaxf(mx, sm.Ss[r][c]);
            float corr = __expf(mo - mx);
            float ls = 0.0f;
            #pragma unroll 8
            for (int c = 0; c < 64; c++) {
                float p = __expf(sm.Ss[r][c] - mx);
                sm.Ss[r][c] = p;
                ls += p;
            }
            sm.mrow[r] = mx;
            sm.lrow[r] = sm.lrow[r] * corr + ls;
            sm.crow[r] = corr;
        }
        __syncthreads();

        // ---- O = O*corr + P V ----
        #pragma unroll
        for (int i = 0; i < 4; i++) {
            float corr = sm.crow[tr * 4 + i];
            #pragma unroll
            for (int j = 0; j < 16; j++) Oacc[i][j] *= corr;
        }
        #pragma unroll 4
        for (int c = 0; c < 64; c++) {
            float pv[4];
            #pragma unroll
            for (int i = 0; i < 4; i++) pv[i] = sm.Ss[tr * 4 + i][c];
            float rv[16];
            *(float4*)(rv)      = *(const float4*)&sm.Vs[c][td * 16];
            *(float4*)(rv + 4)  = *(const float4*)&sm.Vs[c][td * 16 + 4];
            *(float4*)(rv + 8)  = *(const float4*)&sm.Vs[c][td * 16 + 8];
            *(float4*)(rv + 12) = *(const float4*)&sm.Vs[c][td * 16 + 12];
            #pragma unroll
            for (int i = 0; i < 4; i++)
                #pragma unroll
                for (int j = 0; j < 16; j++)
                    Oacc[i][j] += pv[i] * rv[j];
        }
    }

    // ---- normalize and write ----
    #pragma unroll
    for (int i = 0; i < 4; i++) {
        int r = tr * 4 + i;
        float invl = 1.0f / sm.lrow[r];
        float* dst = o + ((size_t)(b * T_SEQ + qs + r) * H_Q + h) * D_HEAD + td * 16;
        #pragma unroll
        for (int j4 = 0; j4 < 4; j4++) {
            *(float4*)(dst + j4 * 4) = make_float4(
                Oacc[i][j4 * 4 + 0] * invl, Oacc[i][j4 * 4 + 1] * invl,
                Oacc[i][j4 * 4 + 2] * invl, Oacc[i][j4 * 4 + 3] * invl);
        }
    }
}

// ---------------------------------------------------------------------------
// launch
// ---------------------------------------------------------------------------
extern "C" void kernel_launch(void* const* d_in, const int* in_sizes, int n_in,
                              void* d_out, int out_size)
{
    const float* x  = (const float*)d_in[0];
    const float* Wq = (const float*)d_in[1];
    const float* Wk = (const float*)d_in[2];
    const float* Wv = (const float*)d_in[3];
    const float* Wo = (const float*)d_in[4];
    float* out = (float*)d_out;

    float *q, *k, *v, *att;
    cudaGetSymbolAddress((void**)&q,   g_q);
    cudaGetSymbolAddress((void**)&k,   g_k);
    cudaGetSymbolAddress((void**)&v,   g_v);
    cudaGetSymbolAddress((void**)&att, g_att);

    // RoPE tables
    rope_table_kernel<<<(T_SEQ * 64 + 255) / 256, 256>>>();

    // QKV projections (NT GEMM)
    sgemm_nt<<<dim3(E_DIM / 128, M_ROWS / 128), 256>>>(x, Wq, q, M_ROWS, H_Q  * D_HEAD, E_DIM);
    sgemm_nt<<<dim3((H_KV * D_HEAD) / 128, M_ROWS / 128), 256>>>(x, Wk, k, M_ROWS, H_KV * D_HEAD, E_DIM);
    sgemm_nt<<<dim3((H_KV * D_HEAD) / 128, M_ROWS / 128), 256>>>(x, Wv, v, M_ROWS, H_KV * D_HEAD, E_DIM);

    // RoPE
    rope_apply_kernel<<<(M_ROWS * H_Q  * 64) / 256, 256>>>(q, H_Q, 4);
    rope_apply_kernel<<<(M_ROWS * H_KV * 64) / 256, 256>>>(k, H_KV, 2);

    // Attention
    cudaFuncSetAttribute(attn_kernel, cudaFuncAttributeMaxDynamicSharedMemorySize,
                         (int)sizeof(AttnSmem));
    attn_kernel<<<dim3(T_SEQ / 64, H_Q, B_SZ), 128, sizeof(AttnSmem)>>>(q, k, v, att);

    // Output projection
    sgemm_nt<<<dim3(E_DIM / 128, M_ROWS / 128), 256>>>(att, Wo, out, M_ROWS, E_DIM, E_DIM);
}

// round 3
// speedup vs baseline: 2.8791x; 2.8791x over previous
#include <cuda_runtime.h>
#include <cuda_bf16.h>
#include <math.h>
#include <stdint.h>

// Problem constants
#define T_SEQ   2048
#define B_SZ    2
#define E_DIM   2048
#define H_Q     16
#define H_KV    4
#define D_HEAD  128
#define M_ROWS  4096        // B*T
#define WIN     512

// ---------------------------------------------------------------------------
// Scratch (device globals: allocation-free rule)
// ---------------------------------------------------------------------------
__device__ float g_q  [M_ROWS * (H_Q  * D_HEAD)];
__device__ float g_k  [M_ROWS * (H_KV * D_HEAD)];
__device__ float g_v  [M_ROWS * (H_KV * D_HEAD)];
__device__ float g_att[M_ROWS * (H_Q  * D_HEAD)];
__device__ float g_cos[T_SEQ * 64];
__device__ float g_sin[T_SEQ * 64];

__device__ __nv_bfloat16 g_xh [M_ROWS * E_DIM];
__device__ __nv_bfloat16 g_xm [M_ROWS * E_DIM];
__device__ __nv_bfloat16 g_wqh[(H_Q  * D_HEAD) * E_DIM];
__device__ __nv_bfloat16 g_wqm[(H_Q  * D_HEAD) * E_DIM];
__device__ __nv_bfloat16 g_wkh[(H_KV * D_HEAD) * E_DIM];
__device__ __nv_bfloat16 g_wkm[(H_KV * D_HEAD) * E_DIM];
__device__ __nv_bfloat16 g_wvh[(H_KV * D_HEAD) * E_DIM];
__device__ __nv_bfloat16 g_wvm[(H_KV * D_HEAD) * E_DIM];
__device__ __nv_bfloat16 g_woh[E_DIM * E_DIM];
__device__ __nv_bfloat16 g_wom[E_DIM * E_DIM];
__device__ __nv_bfloat16 g_ah [M_ROWS * E_DIM];
__device__ __nv_bfloat16 g_am [M_ROWS * E_DIM];

// ---------------------------------------------------------------------------
// fp32 -> (bf16 hi, bf16 mid) split
// ---------------------------------------------------------------------------
__global__ void split_bf16_kernel(const float* __restrict__ src,
                                  __nv_bfloat16* __restrict__ hi,
                                  __nv_bfloat16* __restrict__ mid, int n)
{
    int i = (blockIdx.x * 256 + threadIdx.x) * 4;
    if (i >= n) return;
    float4 v = *(const float4*)(src + i);
    float vs[4] = {v.x, v.y, v.z, v.w};
    __nv_bfloat16 h[4], m[4];
    #pragma unroll
    for (int j = 0; j < 4; j++) {
        h[j] = __float2bfloat16(vs[j]);
        m[j] = __float2bfloat16(vs[j] - __bfloat162float(h[j]));
    }
    *(__nv_bfloat162*)(hi  + i)     = __nv_bfloat162(h[0], h[1]);
    *(__nv_bfloat162*)(hi  + i + 2) = __nv_bfloat162(h[2], h[3]);
    *(__nv_bfloat162*)(mid + i)     = __nv_bfloat162(m[0], m[1]);
    *(__nv_bfloat162*)(mid + i + 2) = __nv_bfloat162(m[2], m[3]);
}

// ---------------------------------------------------------------------------
// RoPE
// ---------------------------------------------------------------------------
__global__ void rope_table_kernel() {
    int idx = blockIdx.x * 256 + threadIdx.x;
    if (idx >= T_SEQ * 64) return;
    int i = idx & 63;
    int t = idx >> 6;
    float ex = (float)(2 * i) * (1.0f / 128.0f);
    float invf = (float)(1.0 / pow(10000.0, (double)ex));
    float ang = (float)t * invf;
    double s, c;
    sincos((double)ang, &s, &c);
    g_cos[idx] = (float)c;
    g_sin[idx] = (float)s;
}

__global__ void rope_apply_kernel(float* __restrict__ buf, int heads, int hshift) {
    int idx = blockIdx.x * 256 + threadIdx.x;
    int total = M_ROWS * heads * 64;
    if (idx >= total) return;
    int i = idx & 63;
    int h = (idx >> 6) & (heads - 1);
    int m = idx >> (6 + hshift);
    int t = m & (T_SEQ - 1);
    float c = g_cos[t * 64 + i];
    float s = g_sin[t * 64 + i];
    float* p = buf + ((size_t)m * heads + h) * D_HEAD + i;
    float x1 = p[0];
    float x2 = p[64];
    p[0]  = x1 * c - x2 * s;
    p[64] = x2 * c + x1 * s;
}

// ---------------------------------------------------------------------------
// Split-bf16 GEMM (NT): C[M,N] = (Ah+Am)(Bh+Bm)^T, 3 passes (hh + hm + mh).
// Tile 128x128, K-chunk 64 bf16 (128B SW128 rows), 3-stage cp.async ring.
// Two device paths: tcgen05 (sm_103a pass) / mma.sync m16n8k16 (plain sm_103).
// ---------------------------------------------------------------------------
#define GK_BK        64
#define GK_TILE_B    16384
#define GK_STAGE_B   65536
#define GK_SMEM      (2048 + 3 * GK_STAGE_B)

#define SWZ128(o) ((o) ^ (((o) >> 3) & 0x70))

static __device__ __forceinline__ uint64_t make_desc(uint32_t addr) {
    const uint64_t base = (uint64_t(2) << 61) | (uint64_t(1) << 46)
                        | (uint64_t(64) << 32) | (uint64_t(1) << 16);
    return base | ((uint64_t)(addr >> 4) & 0x3FFF);
}

static __device__ __forceinline__ uint32_t s2u(const void* p) {
    uint32_t a;
    asm("{ .reg .u64 t; cvta.to.shared.u64 t, %1; cvt.u32.u64 %0, t; }" : "=r"(a) : "l"(p));
    return a;
}

static __device__ __forceinline__ void mbar_wait(uint32_t mbar, uint32_t parity) {
    asm volatile(
        "{\n\t.reg .pred P;\n\t"
        "LW%=:\n\t"
        "mbarrier.try_wait.parity.shared.b64 P, [%0], %1;\n\t"
        "@!P bra LW%=;\n\t}"
        :: "r"(mbar), "r"(parity) : "memory");
}

// idesc kind::f16: F32 acc, bf16 a/b, N=128, M=128
#define GK_IDESC 0x8200490u

#define LDSM_X4(r, addr)                                                      \
    asm volatile("ldmatrix.sync.aligned.m8n8.x4.shared.b16 {%0,%1,%2,%3}, [%4];" \
        : "=r"((r)[0]), "=r"((r)[1]), "=r"((r)[2]), "=r"((r)[3]) : "r"(addr))

#define MMA16816(d, a, b0, b1)                                                \
    asm volatile("mma.sync.aligned.m16n8k16.row.col.f32.bf16.bf16.f32 "       \
        "{%0,%1,%2,%3}, {%4,%5,%6,%7}, {%8,%9}, {%0,%1,%2,%3};"               \
        : "+f"((d)[0]), "+f"((d)[1]), "+f"((d)[2]), "+f"((d)[3])              \
        : "r"((a)[0]), "r"((a)[1]), "r"((a)[2]), "r"((a)[3]),                 \
          "r"(b0), "r"(b1))

__global__ void __launch_bounds__(256)
tc_gemm(const __nv_bfloat16* __restrict__ Ah, const __nv_bfloat16* __restrict__ Am,
        const __nv_bfloat16* __restrict__ Bh, const __nv_bfloat16* __restrict__ Bm,
        float* __restrict__ C, int M, int N, int K)
{
    extern __shared__ char smem_raw[];
    uint32_t sbase  = (s2u(smem_raw) + 1023) & ~1023u;
    uint32_t hdr    = sbase;
    uint32_t stages = sbase + 1024;

    const int tid  = threadIdx.x;
    const int wid  = tid >> 5;
    const int lane = tid & 31;
    const int bm = blockIdx.y * 128;
    const int bn = blockIdx.x * 128;
    const int NC = K / GK_BK;

    const char* gsrc[4] = {
        (const char*)(Ah + (size_t)bm * K), (const char*)(Am + (size_t)bm * K),
        (const char*)(Bh + (size_t)bn * K), (const char*)(Bm + (size_t)bn * K) };

    const int rowK2 = K * 2;
    const int r0    = tid >> 3;
    const int c16   = (tid & 7) * 16;

    auto load_chunk = [&](int c, int st) {
        uint32_t sb = stages + st * GK_STAGE_B;
        long koff = (long)c * GK_BK * 2;
        #pragma unroll
        for (int t = 0; t < 4; t++) {
            uint32_t tb = sb + t * GK_TILE_B;
            #pragma unroll
            for (int r = 0; r < 4; r++) {
                int row = r0 + r * 32;
                uint32_t dst = tb + SWZ128(row * 128 + c16);
                const char* s = gsrc[t] + (size_t)row * rowK2 + koff + c16;
                asm volatile("cp.async.cg.shared.global [%0], [%1], 16;"
                             :: "r"(dst), "l"(s) : "memory");
            }
        }
    };

#if defined(__CUDA_ARCH__) && defined(__CUDA_ARCH_FEAT_SM103_ALL)
    // ============================ tcgen05 path ============================
    if (wid == 0) {
        asm volatile("tcgen05.alloc.cta_group::1.sync.aligned.shared::cta.b32 [%0], %1;"
                     :: "r"(hdr), "r"(128) : "memory");
    }
    if (tid == 0) {
        #pragma unroll
        for (int s = 0; s < 3; s++)
            asm volatile("mbarrier.init.shared.b64 [%0], %1;"
                         :: "r"(hdr + 16 + 8 * s), "r"(1) : "memory");
    }
    __syncthreads();
    uint32_t tmem;
    asm volatile("ld.shared.b32 %0, [%1];" : "=r"(tmem) : "r"(hdr));

    #pragma unroll
    for (int p = 0; p < 3; p++) {
        load_chunk(p, p);
        asm volatile("cp.async.commit_group;" ::: "memory");
    }

    for (int c = 0; c < NC; c++) {
        int st = c % 3;
        asm volatile("cp.async.wait_group 2;" ::: "memory");
        __syncthreads();
        if (tid == 0) {
            asm volatile("fence.proxy.async.shared::cta;" ::: "memory");
            uint32_t sb = stages + st * GK_STAGE_B;
            uint64_t dAh = make_desc(sb);
            uint64_t dAm = make_desc(sb + GK_TILE_B);
            uint64_t dBh = make_desc(sb + 2 * GK_TILE_B);
            uint64_t dBm = make_desc(sb + 3 * GK_TILE_B);
            uint64_t pa[3] = { dAh, dAh, dAm };
            uint64_t pb[3] = { dBh, dBm, dBh };
            #pragma unroll
            for (int pass = 0; pass < 3; pass++) {
                #pragma unroll
                for (int ks = 0; ks < 4; ks++) {
                    uint32_t acc = (c | pass | ks) ? 1u : 0u;
                    asm volatile(
                        "{\n\t.reg .pred p;\n\t"
                        "setp.ne.u32 p, %4, 0;\n\t"
                        "tcgen05.mma.cta_group::1.kind::f16 [%0], %1, %2, %3, {%5,%5,%5,%5}, p;\n\t}"
                        :: "r"(tmem), "l"(pa[pass] + ks * 2), "l"(pb[pass] + ks * 2),
                           "r"(GK_IDESC), "r"(acc), "r"(0u) : "memory");
                }
            }
            asm volatile("tcgen05.commit.cta_group::1.mbarrier::arrive::one.shared::cluster.b64 [%0];"
                         :: "r"(hdr + 16 + 8 * st) : "memory");
        }
        if (c + 3 < NC) {
            mbar_wait(hdr + 16 + 8 * st, (uint32_t)((c / 3) & 1));
            load_chunk(c + 3, st);
        }
        asm volatile("cp.async.commit_group;" ::: "memory");
    }

    mbar_wait(hdr + 16 + 8 * ((NC - 1) % 3), (uint32_t)(((NC - 1) / 3) & 1));
    asm volatile("tcgen05.fence::after_thread_sync;" ::: "memory");

    if (wid < 4) {
        #pragma unroll
        for (int cb = 0; cb < 4; cb++) {
            uint32_t r[32];
            asm volatile(
                "tcgen05.ld.sync.aligned.32x32b.x32.b32 "
                "{%0, %1, %2, %3, %4, %5, %6, %7, "
                " %8, %9, %10, %11, %12, %13, %14, %15, "
                " %16, %17, %18, %19, %20, %21, %22, %23, "
                " %24, %25, %26, %27, %28, %29, %30, %31}, [%32];"
                : "=r"(r[0]),  "=r"(r[1]),  "=r"(r[2]),  "=r"(r[3]),
                  "=r"(r[4]),  "=r"(r[5]),  "=r"(r[6]),  "=r"(r[7]),
                  "=r"(r[8]),  "=r"(r[9]),  "=r"(r[10]), "=r"(r[11]),
                  "=r"(r[12]), "=r"(r[13]), "=r"(r[14]), "=r"(r[15]),
                  "=r"(r[16]), "=r"(r[17]), "=r"(r[18]), "=r"(r[19]),
                  "=r"(r[20]), "=r"(r[21]), "=r"(r[22]), "=r"(r[23]),
                  "=r"(r[24]), "=r"(r[25]), "=r"(r[26]), "=r"(r[27]),
                  "=r"(r[28]), "=r"(r[29]), "=r"(r[30]), "=r"(r[31])
                : "r"(tmem + cb * 32));
            asm volatile("tcgen05.wait::ld.sync.aligned;" ::: "memory");
            int row = bm + wid * 32 + lane;
            float* dst = C + (size_t)row * N + bn + cb * 32;
            #pragma unroll
            for (int q4 = 0; q4 < 8; q4++) {
                float4 v;
                v.x = __uint_as_float(r[q4 * 4 + 0]);
                v.y = __uint_as_float(r[q4 * 4 + 1]);
                v.z = __uint_as_float(r[q4 * 4 + 2]);
                v.w = __uint_as_float(r[q4 * 4 + 3]);
                *(float4*)(dst + q4 * 4) = v;
            }
        }
    }
    __syncthreads();
    if (wid == 0) {
        asm volatile("tcgen05.dealloc.cta_group::1.sync.aligned.b32 %0, %1;"
                     :: "r"(tmem), "r"(128));
    }
#else
    // ====================== mma.sync m16n8k16 fallback ======================
    (void)hdr;
    const int wm = wid >> 2;        // 0..1 : m-block of 64
    const int wn = wid & 3;         // 0..3 : n-block of 32

    float acc[4][4][4];
    #pragma unroll
    for (int mt = 0; mt < 4; mt++)
        #pragma unroll
        for (int nt = 0; nt < 4; nt++)
            #pragma unroll
            for (int e = 0; e < 4; e++) acc[mt][nt][e] = 0.0f;

    #pragma unroll
    for (int p = 0; p < 3; p++) {
        load_chunk(p, p);
        asm volatile("cp.async.commit_group;" ::: "memory");
    }

    // ldmatrix address components (invariant across chunks)
    const int a_row  = wm * 64 + (lane & 15);       // + mt*16
    const int a_byte = (lane >> 4) * 16;            // + ks*32
    const int b_row  = wn * 32 + (lane & 7) + ((lane >> 4) << 3);  // + g*16
    const int b_byte = ((lane >> 3) & 1) << 4;      // + ks*32

    for (int c = 0; c < NC; c++) {
        int st = c % 3;
        asm volatile("cp.async.wait_group 2;" ::: "memory");
        __syncthreads();

        uint32_t sb  = stages + st * GK_STAGE_B;
        uint32_t tAh = sb;
        uint32_t tAm = sb + GK_TILE_B;
        uint32_t tBh = sb + 2 * GK_TILE_B;
        uint32_t tBm = sb + 3 * GK_TILE_B;

        #pragma unroll
        for (int ks = 0; ks < 4; ks++) {
            const int kb = ks * 32;
            uint32_t a_h[4][4], a_m[4][4], b_h[2][4], b_m[2][4];
            #pragma unroll
            for (int mt = 0; mt < 4; mt++) {
                uint32_t off = SWZ128((a_row + mt * 16) * 128 + kb + a_byte);
                LDSM_X4(a_h[mt], tAh + off);
                LDSM_X4(a_m[mt], tAm + off);
            }
            #pragma unroll
            for (int g = 0; g < 2; g++) {
                uint32_t off = SWZ128((b_row + g * 16) * 128 + kb + b_byte);
                LDSM_X4(b_h[g], tBh + off);
                LDSM_X4(b_m[g], tBm + off);
            }
            #pragma unroll
            for (int mt = 0; mt < 4; mt++) {
                #pragma unroll
                for (int nt = 0; nt < 4; nt++) {
                    const int g = nt >> 1;
                    const int o = (nt & 1) * 2;
                    MMA16816(acc[mt][nt], a_h[mt], b_h[g][o], b_h[g][o + 1]);
                    MMA16816(acc[mt][nt], a_h[mt], b_m[g][o], b_m[g][o + 1]);
                    MMA16816(acc[mt][nt], a_m[mt], b_h[g][o], b_h[g][o + 1]);
                }
            }
        }
        __syncthreads();
        if (c + 3 < NC) load_chunk(c + 3, st);
        asm volatile("cp.async.commit_group;" ::: "memory");
    }

    // epilogue: fragment layout (row = lane/4 (+8), col = (lane%4)*2)
    #pragma unroll
    for (int mt = 0; mt < 4; mt++) {
        #pragma unroll
        for (int nt = 0; nt < 4; nt++) {
            int rr = bm + wm * 64 + mt * 16 + (lane >> 2);
            int cc = bn + wn * 32 + nt * 8 + (lane & 3) * 2;
            *(float2*)(C + (size_t)rr * N + cc) =
                make_float2(acc[mt][nt][0], acc[mt][nt][1]);
            *(float2*)(C + (size_t)(rr + 8) * N + cc) =
                make_float2(acc[mt][nt][2], acc[mt][nt][3]);
        }
    }
#endif
}

// ---------------------------------------------------------------------------
// Attention (unchanged, known-good fp32 flash-style)
// ---------------------------------------------------------------------------
struct AttnSmem {
    float Qt[128][64];
    float Kt[128][64];
    float Vs[64][128];
    float Ss[64][65];
    float mrow[64];
    float lrow[64];
    float crow[64];
};

__global__ void __launch_bounds__(128) attn_kernel(
    const float* __restrict__ q, const float* __restrict__ k,
    const float* __restrict__ v, float* __restrict__ o)
{
    extern __shared__ char smem_raw[];
    AttnSmem& sm = *reinterpret_cast<AttnSmem*>(smem_raw);

    const int tid = threadIdx.x;
    const int qs  = blockIdx.x * 64;
    const int h   = blockIdx.y;
    const int b   = blockIdx.z;
    const int kvh = h >> 2;
    const float scale = 0.08838834764831845f;

    {
        int r  = tid >> 1;
        int dh = (tid & 1) * 64;
        const float* src = q + ((size_t)(b * T_SEQ + qs + r) * H_Q + h) * D_HEAD + dh;
        #pragma unroll
        for (int j = 0; j < 16; j++) {
            float4 t4 = *(const float4*)(src + j * 4);
            sm.Qt[dh + j * 4 + 0][r] = t4.x;
            sm.Qt[dh + j * 4 + 1][r] = t4.y;
            sm.Qt[dh + j * 4 + 2][r] = t4.z;
            sm.Qt[dh + j * 4 + 3][r] = t4.w;
        }
    }
    if (tid < 64) { sm.mrow[tid] = -1e30f; sm.lrow[tid] = 0.0f; }

    const int tq = tid & 15;
    const int tk = tid >> 4;
    const int tr = tid & 15;
    const int td = tid >> 4;

    float Oacc[4][16];
    #pragma unroll
    for (int i = 0; i < 4; i++)
        #pragma unroll
        for (int j = 0; j < 16; j++) Oacc[i][j] = 0.0f;

    int kb0 = qs - WIN; if (kb0 < 0) kb0 = 0;

    for (int kb = kb0; kb <= qs; kb += 64) {
        __syncthreads();
        {
            int r  = tid >> 1;
            int dh = (tid & 1) * 64;
            const float* ksrc = k + ((size_t)(b * T_SEQ + kb + r) * H_KV + kvh) * D_HEAD + dh;
            const float* vsrc = v + ((size_t)(b * T_SEQ + kb + r) * H_KV + kvh) * D_HEAD + dh;
            #pragma unroll
            for (int j = 0; j < 16; j++) {
                float4 t4 = *(const float4*)(ksrc + j * 4);
                sm.Kt[dh + j * 4 + 0][r] = t4.x;
                sm.Kt[dh + j * 4 + 1][r] = t4.y;
                sm.Kt[dh + j * 4 + 2][r] = t4.z;
                sm.Kt[dh + j * 4 + 3][r] = t4.w;
            }
            #pragma unroll
            for (int j = 0; j < 16; j++) {
                *(float4*)&sm.Vs[r][dh + j * 4] = *(const float4*)(vsrc + j * 4);
            }
        }
        __syncthreads();

        float sacc[4][8];
        #pragma unroll
        for (int i = 0; i < 4; i++)
            #pragma unroll
            for (int j = 0; j < 8; j++) sacc[i][j] = 0.0f;

        #pragma unroll 4
        for (int d = 0; d < 128; d++) {
            float ra[4], rb[8];
            *(float4*)(ra)     = *(const float4*)&sm.Qt[d][tq * 4];
            *(float4*)(rb)     = *(const float4*)&sm.Kt[d][tk * 8];
            *(float4*)(rb + 4) = *(const float4*)&sm.Kt[d][tk * 8 + 4];
            #pragma unroll
            for (int i = 0; i < 4; i++)
                #pragma unroll
                for (int j = 0; j < 8; j++)
                    sacc[i][j] += ra[i] * rb[j];
        }

        #pragma unroll
        for (int i = 0; i < 4; i++) {
            int qr = qs + tq * 4 + i;
            #pragma unroll
            for (int j = 0; j < 8; j++) {
                int kc = kb + tk * 8 + j;
                bool valid = (kc <= qr) && (qr - kc < WIN);
                sm.Ss[tq * 4 + i][tk * 8 + j] = valid ? sacc[i][j] * scale : -1e30f;
            }
        }
        __syncthreads();

        if (tid < 64) {
            int r = tid;
            float mo = sm.mrow[r];
            float mx = mo;
            #pragma unroll 8
            for (int c = 0; c < 64; c++) mx = fmaxf(mx, sm.Ss[r][c]);
            float corr = __expf(mo - mx);
            float ls = 0.0f;
            #pragma unroll 8
            for (int c = 0; c < 64; c++) {
                float p = __expf(sm.Ss[r][c] - mx);
                sm.Ss[r][c] = p;
                ls += p;
            }
            sm.mrow[r] = mx;
            sm.lrow[r] = sm.lrow[r] * corr + ls;
            sm.crow[r] = corr;
        }
        __syncthreads();

        #pragma unroll
        for (int i = 0; i < 4; i++) {
            float corr = sm.crow[tr * 4 + i];
            #pragma unroll
            for (int j = 0; j < 16; j++) Oacc[i][j] *= corr;
        }
        #pragma unroll 4
        for (int c = 0; c < 64; c++) {
            float pv[4];
            #pragma unroll
            for (int i = 0; i < 4; i++) pv[i] = sm.Ss[tr * 4 + i][c];
            float rv[16];
            *(float4*)(rv)      = *(const float4*)&sm.Vs[c][td * 16];
            *(float4*)(rv + 4)  = *(const float4*)&sm.Vs[c][td * 16 + 4];
            *(float4*)(rv + 8)  = *(const float4*)&sm.Vs[c][td * 16 + 8];
            *(float4*)(rv + 12) = *(const float4*)&sm.Vs[c][td * 16 + 12];
            #pragma unroll
            for (int i = 0; i < 4; i++)
                #pragma unroll
                for (int j = 0; j < 16; j++)
                    Oacc[i][j] += pv[i] * rv[j];
        }
    }

    #pragma unroll
    for (int i = 0; i < 4; i++) {
        int r = tr * 4 + i;
        float invl = 1.0f / sm.lrow[r];
        float* dst = o + ((size_t)(b * T_SEQ + qs + r) * H_Q + h) * D_HEAD + td * 16;
        #pragma unroll
        for (int j4 = 0; j4 < 4; j4++) {
            *(float4*)(dst + j4 * 4) = make_float4(
                Oacc[i][j4 * 4 + 0] * invl, Oacc[i][j4 * 4 + 1] * invl,
                Oacc[i][j4 * 4 + 2] * invl, Oacc[i][j4 * 4 + 3] * invl);
        }
    }
}

// ---------------------------------------------------------------------------
// launch
// ---------------------------------------------------------------------------
extern "C" void kernel_launch(void* const* d_in, const int* in_sizes, int n_in,
                              void* d_out, int out_size)
{
    const float* x  = (const float*)d_in[0];
    const float* Wq = (const float*)d_in[1];
    const float* Wk = (const float*)d_in[2];
    const float* Wv = (const float*)d_in[3];
    const float* Wo = (const float*)d_in[4];
    float* out = (float*)d_out;

    float *q, *k, *v, *att;
    cudaGetSymbolAddress((void**)&q,   g_q);
    cudaGetSymbolAddress((void**)&k,   g_k);
    cudaGetSymbolAddress((void**)&v,   g_v);
    cudaGetSymbolAddress((void**)&att, g_att);

    __nv_bfloat16 *xh, *xm, *wqh, *wqm, *wkh, *wkm, *wvh, *wvm, *woh, *wom, *ah, *am;
    cudaGetSymbolAddress((void**)&xh,  g_xh);  cudaGetSymbolAddress((void**)&xm,  g_xm);
    cudaGetSymbolAddress((void**)&wqh, g_wqh); cudaGetSymbolAddress((void**)&wqm, g_wqm);
    cudaGetSymbolAddress((void**)&wkh, g_wkh); cudaGetSymbolAddress((void**)&wkm, g_wkm);
    cudaGetSymbolAddress((void**)&wvh, g_wvh); cudaGetSymbolAddress((void**)&wvm, g_wvm);
    cudaGetSymbolAddress((void**)&woh, g_woh); cudaGetSymbolAddress((void**)&wom, g_wom);
    cudaGetSymbolAddress((void**)&ah,  g_ah);  cudaGetSymbolAddress((void**)&am,  g_am);

    cudaFuncSetAttribute(tc_gemm, cudaFuncAttributeMaxDynamicSharedMemorySize, GK_SMEM);
    cudaFuncSetAttribute(attn_kernel, cudaFuncAttributeMaxDynamicSharedMemorySize,
                         (int)sizeof(AttnSmem));

    rope_table_kernel<<<(T_SEQ * 64 + 255) / 256, 256>>>();

    int nx = M_ROWS * E_DIM;
    int nq = H_Q * D_HEAD * E_DIM;
    int nk = H_KV * D_HEAD * E_DIM;
    split_bf16_kernel<<<(nx / 4 + 255) / 256, 256>>>(x,  xh,  xm,  nx);
    split_bf16_kernel<<<(nq / 4 + 255) / 256, 256>>>(Wq, wqh, wqm, nq);
    split_bf16_kernel<<<(nk / 4 + 255) / 256, 256>>>(Wk, wkh, wkm, nk);
    split_bf16_kernel<<<(nk / 4 + 255) / 256, 256>>>(Wv, wvh, wvm, nk);
    split_bf16_kernel<<<(nq / 4 + 255) / 256, 256>>>(Wo, woh, wom, nq);

    tc_gemm<<<dim3(E_DIM / 128, M_ROWS / 128), 256, GK_SMEM>>>(
        xh, xm, wqh, wqm, q, M_ROWS, H_Q * D_HEAD, E_DIM);
    tc_gemm<<<dim3((H_KV * D_HEAD) / 128, M_ROWS / 128), 256, GK_SMEM>>>(
        xh, xm, wkh, wkm, k, M_ROWS, H_KV * D_HEAD, E_DIM);
    tc_gemm<<<dim3((H_KV * D_HEAD) / 128, M_ROWS / 128), 256, GK_SMEM>>>(
        xh, xm, wvh, wvm, v, M_ROWS, H_KV * D_HEAD, E_DIM);

    rope_apply_kernel<<<(M_ROWS * H_Q  * 64) / 256, 256>>>(q, H_Q, 4);
    rope_apply_kernel<<<(M_ROWS * H_KV * 64) / 256, 256>>>(k, H_KV, 2);

    attn_kernel<<<dim3(T_SEQ / 64, H_Q, B_SZ), 128, sizeof(AttnSmem)>>>(q, k, v, att);

    split_bf16_kernel<<<(nx / 4 + 255) / 256, 256>>>(att, ah, am, nx);
    tc_gemm<<<dim3(E_DIM / 128, M_ROWS / 128), 256, GK_SMEM>>>(
        ah, am, woh, wom, out, M_ROWS, E_DIM, E_DIM);
}

// round 5
// speedup vs baseline: 4.9754x; 1.7281x over previous
#include <cuda_runtime.h>
#include <cuda_bf16.h>
#include <math.h>
#include <stdint.h>

// Problem constants
#define T_SEQ   2048
#define B_SZ    2
#define E_DIM   2048
#define H_Q     16
#define H_KV    4
#define D_HEAD  128
#define M_ROWS  4096        // B*T
#define WIN     512

// ---------------------------------------------------------------------------
// Scratch (device globals: allocation-free rule)
// ---------------------------------------------------------------------------
__device__ float g_q  [M_ROWS * (H_Q  * D_HEAD)];
__device__ float g_k  [M_ROWS * (H_KV * D_HEAD)];
__device__ float g_v  [M_ROWS * (H_KV * D_HEAD)];
__device__ float g_att[M_ROWS * (H_Q  * D_HEAD)];
__device__ float g_cos[T_SEQ * 64];
__device__ float g_sin[T_SEQ * 64];

__device__ __nv_bfloat16 g_xh [M_ROWS * E_DIM];
__device__ __nv_bfloat16 g_xm [M_ROWS * E_DIM];
__device__ __nv_bfloat16 g_wqh[(H_Q  * D_HEAD) * E_DIM];
__device__ __nv_bfloat16 g_wqm[(H_Q  * D_HEAD) * E_DIM];
__device__ __nv_bfloat16 g_wkh[(H_KV * D_HEAD) * E_DIM];
__device__ __nv_bfloat16 g_wkm[(H_KV * D_HEAD) * E_DIM];
__device__ __nv_bfloat16 g_wvh[(H_KV * D_HEAD) * E_DIM];
__device__ __nv_bfloat16 g_wvm[(H_KV * D_HEAD) * E_DIM];
__device__ __nv_bfloat16 g_woh[E_DIM * E_DIM];
__device__ __nv_bfloat16 g_wom[E_DIM * E_DIM];
__device__ __nv_bfloat16 g_ah [M_ROWS * E_DIM];
__device__ __nv_bfloat16 g_am [M_ROWS * E_DIM];

// attention operands, head-major bf16
__device__ __nv_bfloat16 g_qbf[B_SZ * H_Q  * T_SEQ * D_HEAD];  // [b][h][t][d], RoPE'd
__device__ __nv_bfloat16 g_kbf[B_SZ * H_KV * T_SEQ * D_HEAD];  // [b][kv][t][d], RoPE'd
__device__ __nv_bfloat16 g_vth[B_SZ * H_KV * D_HEAD * T_SEQ];  // [b][kv][d][t] hi
__device__ __nv_bfloat16 g_vtm[B_SZ * H_KV * D_HEAD * T_SEQ];  // [b][kv][d][t] mid

// ---------------------------------------------------------------------------
// fp32 -> (bf16 hi, bf16 mid) split
// ---------------------------------------------------------------------------
__global__ void split_bf16_kernel(const float* __restrict__ src,
                                  __nv_bfloat16* __restrict__ hi,
                                  __nv_bfloat16* __restrict__ mid, int n)
{
    int i = (blockIdx.x * 256 + threadIdx.x) * 4;
    if (i >= n) return;
    float4 v = *(const float4*)(src + i);
    float vs[4] = {v.x, v.y, v.z, v.w};
    __nv_bfloat16 h[4], m[4];
    #pragma unroll
    for (int j = 0; j < 4; j++) {
        h[j] = __float2bfloat16(vs[j]);
        m[j] = __float2bfloat16(vs[j] - __bfloat162float(h[j]));
    }
    *(__nv_bfloat162*)(hi  + i)     = __nv_bfloat162(h[0], h[1]);
    *(__nv_bfloat162*)(hi  + i + 2) = __nv_bfloat162(h[2], h[3]);
    *(__nv_bfloat162*)(mid + i)     = __nv_bfloat162(m[0], m[1]);
    *(__nv_bfloat162*)(mid + i + 2) = __nv_bfloat162(m[2], m[3]);
}

// ---------------------------------------------------------------------------
// RoPE tables
// ---------------------------------------------------------------------------
__global__ void rope_table_kernel() {
    int idx = blockIdx.x * 256 + threadIdx.x;
    if (idx >= T_SEQ * 64) return;
    int i = idx & 63;
    int t = idx >> 6;
    float ex = (float)(2 * i) * (1.0f / 128.0f);
    float invf = (float)(1.0 / pow(10000.0, (double)ex));
    float ang = (float)t * invf;
    double s, c;
    sincos((double)ang, &s, &c);
    g_cos[idx] = (float)c;
    g_sin[idx] = (float)s;
}

// ---------------------------------------------------------------------------
// Pack Q: fp32 [t][h][d] -> RoPE -> bf16 [b][h][t][d]
// ---------------------------------------------------------------------------
__global__ void pack_q_kernel(const float* __restrict__ q, __nv_bfloat16* __restrict__ o) {
    int idx = blockIdx.x * 256 + threadIdx.x;        // B*T*H*64 = 4194304
    int i = idx & 63;
    int h = (idx >> 6) & 15;
    int t = (idx >> 10) & 2047;
    int b = idx >> 21;
    float c = g_cos[t * 64 + i];
    float s = g_sin[t * 64 + i];
    const float* p = q + ((size_t)((b * T_SEQ + t) * H_Q + h)) * D_HEAD + i;
    float x1 = p[0], x2 = p[64];
    __nv_bfloat16* d = o + ((size_t)(b * H_Q + h) * T_SEQ + t) * D_HEAD + i;
    d[0]  = __float2bfloat16(x1 * c - x2 * s);
    d[64] = __float2bfloat16(x2 * c + x1 * s);
}

// Pack K: fp32 [t][kv][d] -> RoPE -> bf16 [b][kv][t][d]
__global__ void pack_k_kernel(const float* __restrict__ k, __nv_bfloat16* __restrict__ o) {
    int idx = blockIdx.x * 256 + threadIdx.x;        // B*T*KV*64 = 1048576
    int i = idx & 63;
    int kv = (idx >> 6) & 3;
    int t = (idx >> 8) & 2047;
    int b = idx >> 19;
    float c = g_cos[t * 64 + i];
    float s = g_sin[t * 64 + i];
    const float* p = k + ((size_t)((b * T_SEQ + t) * H_KV + kv)) * D_HEAD + i;
    float x1 = p[0], x2 = p[64];
    __nv_bfloat16* d = o + ((size_t)(b * H_KV + kv) * T_SEQ + t) * D_HEAD + i;
    d[0]  = __float2bfloat16(x1 * c - x2 * s);
    d[64] = __float2bfloat16(x2 * c + x1 * s);
}

// Pack V: fp32 [t][kv][d] -> transpose+split -> bf16 hi/mid [b][kv][d][t]
__global__ void pack_v_kernel(const float* __restrict__ v,
                              __nv_bfloat16* __restrict__ vth,
                              __nv_bfloat16* __restrict__ vtm)
{
    __shared__ float tile[64][65];
    int t0 = blockIdx.x * 64;
    int d0 = blockIdx.y * 64;
    int bk = blockIdx.z;             // b*4 + kv
    int b = bk >> 2, kv = bk & 3;
    int tr = threadIdx.x >> 4;
    int c4 = (threadIdx.x & 15) * 4;
    #pragma unroll
    for (int r = 0; r < 4; r++) {
        int t = t0 + tr + r * 16;
        float4 val = *(const float4*)&v[((size_t)(b * T_SEQ + t) * H_KV + kv) * D_HEAD + d0 + c4];
        tile[tr + r * 16][c4 + 0] = val.x;
        tile[tr + r * 16][c4 + 1] = val.y;
        tile[tr + r * 16][c4 + 2] = val.z;
        tile[tr + r * 16][c4 + 3] = val.w;
    }
    __syncthreads();
    int dr = threadIdx.x >> 2;
    int cg = (threadIdx.x & 3) * 16;
    size_t obase = ((size_t)bk * D_HEAD + d0 + dr) * T_SEQ + t0 + cg;
    #pragma unroll
    for (int j = 0; j < 16; j++) {
        float x = tile[cg + j][dr];
        __nv_bfloat16 h = __float2bfloat16(x);
        vth[obase + j] = h;
        vtm[obase + j] = __float2bfloat16(x - __bfloat162float(h));
    }
}

// ---------------------------------------------------------------------------
// Split-bf16 GEMM (NT) — unchanged from R3 (passing)
// ---------------------------------------------------------------------------
#define GK_BK        64
#define GK_TILE_B    16384
#define GK_STAGE_B   65536
#define GK_SMEM      (2048 + 3 * GK_STAGE_B)

#define SWZ128(o) ((o) ^ (((o) >> 3) & 0x70))

static __device__ __forceinline__ uint64_t make_desc(uint32_t addr) {
    const uint64_t base = (uint64_t(2) << 61) | (uint64_t(1) << 46)
                        | (uint64_t(64) << 32) | (uint64_t(1) << 16);
    return base | ((uint64_t)(addr >> 4) & 0x3FFF);
}

static __device__ __forceinline__ uint32_t s2u(const void* p) {
    uint32_t a;
    asm("{ .reg .u64 t; cvta.to.shared.u64 t, %1; cvt.u32.u64 %0, t; }" : "=r"(a) : "l"(p));
    return a;
}

static __device__ __forceinline__ void mbar_wait(uint32_t mbar, uint32_t parity) {
    asm volatile(
        "{\n\t.reg .pred P;\n\t"
        "LW%=:\n\t"
        "mbarrier.try_wait.parity.shared.b64 P, [%0], %1;\n\t"
        "@!P bra LW%=;\n\t}"
        :: "r"(mbar), "r"(parity) : "memory");
}

#define GK_IDESC 0x8200490u

#define LDSM_X4(r, addr)                                                      \
    asm volatile("ldmatrix.sync.aligned.m8n8.x4.shared.b16 {%0,%1,%2,%3}, [%4];" \
        : "=r"((r)[0]), "=r"((r)[1]), "=r"((r)[2]), "=r"((r)[3]) : "r"(addr))

#define MMA16816(d, a, b0, b1)                                                \
    asm volatile("mma.sync.aligned.m16n8k16.row.col.f32.bf16.bf16.f32 "       \
        "{%0,%1,%2,%3}, {%4,%5,%6,%7}, {%8,%9}, {%0,%1,%2,%3};"               \
        : "+f"((d)[0]), "+f"((d)[1]), "+f"((d)[2]), "+f"((d)[3])              \
        : "r"((a)[0]), "r"((a)[1]), "r"((a)[2]), "r"((a)[3]),                 \
          "r"(b0), "r"(b1))

__global__ void __launch_bounds__(256)
tc_gemm(const __nv_bfloat16* __restrict__ Ah, const __nv_bfloat16* __restrict__ Am,
        const __nv_bfloat16* __restrict__ Bh, const __nv_bfloat16* __restrict__ Bm,
        float* __restrict__ C, int M, int N, int K)
{
    extern __shared__ char smem_raw[];
    uint32_t sbase  = (s2u(smem_raw) + 1023) & ~1023u;
    uint32_t hdr    = sbase;
    uint32_t stages = sbase + 1024;

    const int tid  = threadIdx.x;
    const int wid  = tid >> 5;
    const int lane = tid & 31;
    const int bm = blockIdx.y * 128;
    const int bn = blockIdx.x * 128;
    const int NC = K / GK_BK;

    const char* gsrc[4] = {
        (const char*)(Ah + (size_t)bm * K), (const char*)(Am + (size_t)bm * K),
        (const char*)(Bh + (size_t)bn * K), (const char*)(Bm + (size_t)bn * K) };

    const int rowK2 = K * 2;
    const int r0    = tid >> 3;
    const int c16   = (tid & 7) * 16;

    auto load_chunk = [&](int c, int st) {
        uint32_t sb = stages + st * GK_STAGE_B;
        long koff = (long)c * GK_BK * 2;
        #pragma unroll
        for (int t = 0; t < 4; t++) {
            uint32_t tb = sb + t * GK_TILE_B;
            #pragma unroll
            for (int r = 0; r < 4; r++) {
                int row = r0 + r * 32;
                uint32_t dst = tb + SWZ128(row * 128 + c16);
                const char* s = gsrc[t] + (size_t)row * rowK2 + koff + c16;
                asm volatile("cp.async.cg.shared.global [%0], [%1], 16;"
                             :: "r"(dst), "l"(s) : "memory");
            }
        }
    };

#if defined(__CUDA_ARCH__) && defined(__CUDA_ARCH_FEAT_SM103_ALL)
    // ============================ tcgen05 path ============================
    if (wid == 0) {
        asm volatile("tcgen05.alloc.cta_group::1.sync.aligned.shared::cta.b32 [%0], %1;"
                     :: "r"(hdr), "r"(128) : "memory");
    }
    if (tid == 0) {
        #pragma unroll
        for (int s = 0; s < 3; s++)
            asm volatile("mbarrier.init.shared.b64 [%0], %1;"
                         :: "r"(hdr + 16 + 8 * s), "r"(1) : "memory");
    }
    __syncthreads();
    uint32_t tmem;
    asm volatile("ld.shared.b32 %0, [%1];" : "=r"(tmem) : "r"(hdr));

    #pragma unroll
    for (int p = 0; p < 3; p++) {
        load_chunk(p, p);
        asm volatile("cp.async.commit_group;" ::: "memory");
    }

    for (int c = 0; c < NC; c++) {
        int st = c % 3;
        asm volatile("cp.async.wait_group 2;" ::: "memory");
        __syncthreads();
        if (tid == 0) {
            asm volatile("fence.proxy.async.shared::cta;" ::: "memory");
            uint32_t sb = stages + st * GK_STAGE_B;
            uint64_t dAh = make_desc(sb);
            uint64_t dAm = make_desc(sb + GK_TILE_B);
            uint64_t dBh = make_desc(sb + 2 * GK_TILE_B);
            uint64_t dBm = make_desc(sb + 3 * GK_TILE_B);
            uint64_t pa[3] = { dAh, dAh, dAm };
            uint64_t pb[3] = { dBh, dBm, dBh };
            #pragma unroll
            for (int pass = 0; pass < 3; pass++) {
                #pragma unroll
                for (int ks = 0; ks < 4; ks++) {
                    uint32_t acc = (c | pass | ks) ? 1u : 0u;
                    asm volatile(
                        "{\n\t.reg .pred p;\n\t"
                        "setp.ne.u32 p, %4, 0;\n\t"
                        "tcgen05.mma.cta_group::1.kind::f16 [%0], %1, %2, %3, {%5,%5,%5,%5}, p;\n\t}"
                        :: "r"(tmem), "l"(pa[pass] + ks * 2), "l"(pb[pass] + ks * 2),
                           "r"(GK_IDESC), "r"(acc), "r"(0u) : "memory");
                }
            }
            asm volatile("tcgen05.commit.cta_group::1.mbarrier::arrive::one.shared::cluster.b64 [%0];"
                         :: "r"(hdr + 16 + 8 * st) : "memory");
        }
        if (c + 3 < NC) {
            mbar_wait(hdr + 16 + 8 * st, (uint32_t)((c / 3) & 1));
            load_chunk(c + 3, st);
        }
        asm volatile("cp.async.commit_group;" ::: "memory");
    }

    mbar_wait(hdr + 16 + 8 * ((NC - 1) % 3), (uint32_t)(((NC - 1) / 3) & 1));
    asm volatile("tcgen05.fence::after_thread_sync;" ::: "memory");

    if (wid < 4) {
        #pragma unroll
        for (int cb = 0; cb < 4; cb++) {
            uint32_t r[32];
            asm volatile(
                "tcgen05.ld.sync.aligned.32x32b.x32.b32 "
                "{%0, %1, %2, %3, %4, %5, %6, %7, "
                " %8, %9, %10, %11, %12, %13, %14, %15, "
                " %16, %17, %18, %19, %20, %21, %22, %23, "
                " %24, %25, %26, %27, %28, %29, %30, %31}, [%32];"
                : "=r"(r[0]),  "=r"(r[1]),  "=r"(r[2]),  "=r"(r[3]),
                  "=r"(r[4]),  "=r"(r[5]),  "=r"(r[6]),  "=r"(r[7]),
                  "=r"(r[8]),  "=r"(r[9]),  "=r"(r[10]), "=r"(r[11]),
                  "=r"(r[12]), "=r"(r[13]), "=r"(r[14]), "=r"(r[15]),
                  "=r"(r[16]), "=r"(r[17]), "=r"(r[18]), "=r"(r[19]),
                  "=r"(r[20]), "=r"(r[21]), "=r"(r[22]), "=r"(r[23]),
                  "=r"(r[24]), "=r"(r[25]), "=r"(r[26]), "=r"(r[27]),
                  "=r"(r[28]), "=r"(r[29]), "=r"(r[30]), "=r"(r[31])
                : "r"(tmem + cb * 32));
            asm volatile("tcgen05.wait::ld.sync.aligned;" ::: "memory");
            int row = bm + wid * 32 + lane;
            float* dst = C + (size_t)row * N + bn + cb * 32;
            #pragma unroll
            for (int q4 = 0; q4 < 8; q4++) {
                float4 v;
                v.x = __uint_as_float(r[q4 * 4 + 0]);
                v.y = __uint_as_float(r[q4 * 4 + 1]);
                v.z = __uint_as_float(r[q4 * 4 + 2]);
                v.w = __uint_as_float(r[q4 * 4 + 3]);
                *(float4*)(dst + q4 * 4) = v;
            }
        }
    }
    __syncthreads();
    if (wid == 0) {
        asm volatile("tcgen05.dealloc.cta_group::1.sync.aligned.b32 %0, %1;"
                     :: "r"(tmem), "r"(128));
    }
#else
    // ====================== mma.sync m16n8k16 fallback ======================
    (void)hdr;
    const int wm = wid >> 2;
    const int wn = wid & 3;

    float acc[4][4][4];
    #pragma unroll
    for (int mt = 0; mt < 4; mt++)
        #pragma unroll
        for (int nt = 0; nt < 4; nt++)
            #pragma unroll
            for (int e = 0; e < 4; e++) acc[mt][nt][e] = 0.0f;

    #pragma unroll
    for (int p = 0; p < 3; p++) {
        load_chunk(p, p);
        asm volatile("cp.async.commit_group;" ::: "memory");
    }

    const int a_row  = wm * 64 + (lane & 15);
    const int a_byte = (lane >> 4) * 16;
    const int b_row  = wn * 32 + (lane & 7) + ((lane >> 4) << 3);
    const int b_byte = ((lane >> 3) & 1) << 4;

    for (int c = 0; c < NC; c++) {
        int st = c % 3;
        asm volatile("cp.async.wait_group 2;" ::: "memory");
        __syncthreads();

        uint32_t sb  = stages + st * GK_STAGE_B;
        uint32_t tAh = sb;
        uint32_t tAm = sb + GK_TILE_B;
        uint32_t tBh = sb + 2 * GK_TILE_B;
        uint32_t tBm = sb + 3 * GK_TILE_B;

        #pragma unroll
        for (int ks = 0; ks < 4; ks++) {
            const int kb = ks * 32;
            uint32_t a_h[4][4], a_m[4][4], b_h[2][4], b_m[2][4];
            #pragma unroll
            for (int mt = 0; mt < 4; mt++) {
                uint32_t off = SWZ128((a_row + mt * 16) * 128 + kb + a_byte);
                LDSM_X4(a_h[mt], tAh + off);
                LDSM_X4(a_m[mt], tAm + off);
            }
            #pragma unroll
            for (int g = 0; g < 2; g++) {
                uint32_t off = SWZ128((b_row + g * 16) * 128 + kb + b_byte);
                LDSM_X4(b_h[g], tBh + off);
                LDSM_X4(b_m[g], tBm + off);
            }
            #pragma unroll
            for (int mt = 0; mt < 4; mt++) {
                #pragma unroll
                for (int nt = 0; nt < 4; nt++) {
                    const int g = nt >> 1;
                    const int o = (nt & 1) * 2;
                    MMA16816(acc[mt][nt], a_h[mt], b_h[g][o], b_h[g][o + 1]);
                    MMA16816(acc[mt][nt], a_h[mt], b_m[g][o], b_m[g][o + 1]);
                    MMA16816(acc[mt][nt], a_m[mt], b_h[g][o], b_h[g][o + 1]);
                }
            }
        }
        __syncthreads();
        if (c + 3 < NC) load_chunk(c + 3, st);
        asm volatile("cp.async.commit_group;" ::: "memory");
    }

    #pragma unroll
    for (int mt = 0; mt < 4; mt++) {
        #pragma unroll
        for (int nt = 0; nt < 4; nt++) {
            int rr = bm + wm * 64 + mt * 16 + (lane >> 2);
            int cc = bn + wn * 32 + nt * 8 + (lane & 3) * 2;
            *(float2*)(C + (size_t)rr * N + cc) =
                make_float2(acc[mt][nt][0], acc[mt][nt][1]);
            *(float2*)(C + (size_t)(rr + 8) * N + cc) =
                make_float2(acc[mt][nt][2], acc[mt][nt][3]);
        }
    }
#endif
}

// ---------------------------------------------------------------------------
// Tensor-core flash attention (mma.sync m16n8k16 bf16).
// CTA = 64 queries x (head, batch), 4 warps; 64-key blocks, 2-stage cp.async.
// S = Qbf16·Kbf16 (1 pass); PV split-bf16 3-pass (PhVh + PmVh + PhVm).
// smem tiles: Q/K [128 vrows][128B] (vrow = row*2 + dhalf), Vt [d=128][64 keys].
// ---------------------------------------------------------------------------
#define AT_Q_B     16384
#define AT_STG_B   49152            // K(16K) + Vh(16K) + Vm(16K)
#define AT_SMEM    (AT_Q_B + 2 * AT_STG_B)

static __device__ __forceinline__ void split2(float x, float y,
                                              uint32_t& hi, uint32_t& mi) {
    __nv_bfloat162 h;
    h.x = __float2bfloat16(x);
    h.y = __float2bfloat16(y);
    __nv_bfloat162 m;
    m.x = __float2bfloat16(x - __bfloat162float(h.x));
    m.y = __float2bfloat16(y - __bfloat162float(h.y));
    hi = *(uint32_t*)&h;
    mi = *(uint32_t*)&m;
}

__global__ void __launch_bounds__(128, 2) attn_mma_kernel(
    const __nv_bfloat16* __restrict__ qbf, const __nv_bfloat16* __restrict__ kbf,
    const __nv_bfloat16* __restrict__ vth, const __nv_bfloat16* __restrict__ vtm,
    float* __restrict__ o)
{
    extern __shared__ char smem_raw[];
    const uint32_t sb   = s2u(smem_raw);
    const int tid  = threadIdx.x;
    const int w    = tid >> 5;
    const int lane = tid & 31;
    const int qs   = blockIdx.x * 64;
    const int h    = blockIdx.y;
    const int b    = blockIdx.z;
    const int kvh  = h >> 2;
    const float scale = 0.08838834764831845f;

    const char* qb  = (const char*)(qbf + ((size_t)(b * H_Q + h) * T_SEQ + qs) * D_HEAD);
    const char* kb_ = (const char*)(kbf + (size_t)(b * H_KV + kvh) * T_SEQ * D_HEAD);
    const char* vhb = (const char*)(vth + (size_t)(b * H_KV + kvh) * D_HEAD * T_SEQ);
    const char* vmb = (const char*)(vtm + (size_t)(b * H_KV + kvh) * D_HEAD * T_SEQ);

    // FIX: window covers keys >= qs-511 -> first block is floor((qs-512)/64)
    const int kb0 = (qs >= WIN) ? qs - WIN : 0;
    const int NB  = ((qs - kb0) >> 6) + 1;

    auto load_kv = [&](int kb, int st) {
        uint32_t base = sb + AT_Q_B + st * AT_STG_B;
        const char* ks = kb_ + (size_t)kb * 256;           // row kb, 256B/row
        const char* vh = vhb + ((size_t)tid * T_SEQ + kb) * 2;
        const char* vm = vmb + ((size_t)tid * T_SEQ + kb) * 2;
        #pragma unroll
        for (int j = 0; j < 8; j++) {
            uint32_t off = SWZ128(tid * 128 + j * 16);
            asm volatile("cp.async.cg.shared.global [%0], [%1], 16;"
                         :: "r"(base + off), "l"(ks + tid * 128 + j * 16) : "memory");
            asm volatile("cp.async.cg.shared.global [%0], [%1], 16;"
                         :: "r"(base + 16384 + off), "l"(vh + j * 16) : "memory");
            asm volatile("cp.async.cg.shared.global [%0], [%1], 16;"
                         :: "r"(base + 32768 + off), "l"(vm + j * 16) : "memory");
        }
    };

    // group 0: Q tile + first KV block
    #pragma unroll
    for (int j = 0; j < 8; j++) {
        asm volatile("cp.async.cg.shared.global [%0], [%1], 16;"
                     :: "r"(sb + SWZ128(tid * 128 + j * 16)),
                        "l"(qb + tid * 128 + j * 16) : "memory");
    }
    load_kv(kb0, 0);
    asm volatile("cp.async.commit_group;" ::: "memory");
    if (NB > 1) {
        load_kv(kb0 + 64, 1);
        asm volatile("cp.async.commit_group;" ::: "memory");
    }

    float O[16][4];
    #pragma unroll
    for (int nt = 0; nt < 16; nt++)
        #pragma unroll
        for (int e = 0; e < 4; e++) O[nt][e] = 0.0f;
    float m0 = -1e30f, m1 = -1e30f, l0 = 0.0f, l1 = 0.0f;

    const int r0g = qs + w * 16 + (lane >> 2);        // global query rows
    const int r1g = r0g + 8;

    for (int i = 0; i < NB; i++) {
        const int kb = kb0 + i * 64;
        const int st = i & 1;
        if (i + 1 < NB) asm volatile("cp.async.wait_group 1;" ::: "memory");
        else            asm volatile("cp.async.wait_group 0;" ::: "memory");
        __syncthreads();

        const uint32_t kbase = sb + AT_Q_B + st * AT_STG_B;
        const uint32_t vhbase = kbase + 16384;
        const uint32_t vmbase = kbase + 32768;

        // ---- S = Q K^T ----
        float sreg[8][4];
        #pragma unroll
        for (int t = 0; t < 8; t++)
            #pragma unroll
            for (int e = 0; e < 4; e++) sreg[t][e] = 0.0f;

        #pragma unroll
        for (int ks = 0; ks < 8; ks++) {
            const int khalf = ks >> 2;
            const int kb32  = (ks & 3) * 32;
            uint32_t a[4];
            {
                uint32_t vrow = (uint32_t)(w * 16 + (lane & 15)) * 2 + khalf;
                LDSM_X4(a, sb + SWZ128(vrow * 128 + kb32 + (lane >> 4) * 16));
            }
            #pragma unroll
            for (int g = 0; g < 4; g++) {
                uint32_t bf[4];
                uint32_t vrow = (uint32_t)(g * 16 + (lane & 7) + ((lane >> 4) << 3)) * 2 + khalf;
                LDSM_X4(bf, kbase + SWZ128(vrow * 128 + kb32 + (((lane >> 3) & 1) << 4)));
                MMA16816(sreg[g * 2],     a, bf[0], bf[1]);
                MMA16816(sreg[g * 2 + 1], a, bf[2], bf[3]);
            }
        }

        // ---- mask + scale + online softmax ----
        float mx0 = -1e30f, mx1 = -1e30f;
        #pragma unroll
        for (int t = 0; t < 8; t++) {
            int c0 = kb + t * 8 + (lane & 3) * 2;
            int c1 = c0 + 1;
            sreg[t][0] = (c0 <= r0g && r0g - c0 < WIN) ? sreg[t][0] * scale : -1e30f;
            sreg[t][1] = (c1 <= r0g && r0g - c1 < WIN) ? sreg[t][1] * scale : -1e30f;
            sreg[t][2] = (c0 <= r1g && r1g - c0 < WIN) ? sreg[t][2] * scale : -1e30f;
            sreg[t][3] = (c1 <= r1g && r1g - c1 < WIN) ? sreg[t][3] * scale : -1e30f;
            mx0 = fmaxf(mx0, fmaxf(sreg[t][0], sreg[t][1]));
            mx1 = fmaxf(mx1, fmaxf(sreg[t][2], sreg[t][3]));
        }
        mx0 = fmaxf(mx0, __shfl_xor_sync(0xffffffffu, mx0, 1));
        mx0 = fmaxf(mx0, __shfl_xor_sync(0xffffffffu, mx0, 2));
        mx1 = fmaxf(mx1, __shfl_xor_sync(0xffffffffu, mx1, 1));
        mx1 = fmaxf(mx1, __shfl_xor_sync(0xffffffffu, mx1, 2));

        float mn0 = fmaxf(m0, mx0), mn1 = fmaxf(m1, mx1);
        float corr0 = __expf(m0 - mn0), corr1 = __expf(m1 - mn1);
        m0 = mn0; m1 = mn1;

        float sum0 = 0.0f, sum1 = 0.0f;
        #pragma unroll
        for (int t = 0; t < 8; t++) {
            sreg[t][0] = __expf(sreg[t][0] - m0);
            sreg[t][1] = __expf(sreg[t][1] - m0);
            sreg[t][2] = __expf(sreg[t][2] - m1);
            sreg[t][3] = __expf(sreg[t][3] - m1);
            sum0 += sreg[t][0] + sreg[t][1];
            sum1 += sreg[t][2] + sreg[t][3];
        }
        sum0 += __shfl_xor_sync(0xffffffffu, sum0, 1);
        sum0 += __shfl_xor_sync(0xffffffffu, sum0, 2);
        sum1 += __shfl_xor_sync(0xffffffffu, sum1, 1);
        sum1 += __shfl_xor_sync(0xffffffffu, sum1, 2);
        l0 = l0 * corr0 + sum0;
        l1 = l1 * corr1 + sum1;

        #pragma unroll
        for (int nt = 0; nt < 16; nt++) {
            O[nt][0] *= corr0; O[nt][1] *= corr0;
            O[nt][2] *= corr1; O[nt][3] *= corr1;
        }

        // ---- P split into bf16 A-fragments ----
        uint32_t ah[4][4], am[4][4];
        #pragma unroll
        for (int f = 0; f < 4; f++) {
            split2(sreg[2 * f][0],     sreg[2 * f][1],     ah[f][0], am[f][0]);
            split2(sreg[2 * f][2],     sreg[2 * f][3],     ah[f][1], am[f][1]);
            split2(sreg[2 * f + 1][0], sreg[2 * f + 1][1], ah[f][2], am[f][2]);
            split2(sreg[2 * f + 1][2], sreg[2 * f + 1][3], ah[f][3], am[f][3]);
        }

        // ---- O += P V (3 passes) ----
        #pragma unroll
        for (int f = 0; f < 4; f++) {
            #pragma unroll
            for (int g = 0; g < 8; g++) {
                uint32_t bh[4], bm2[4];
                uint32_t vrow = (uint32_t)(g * 16 + (lane & 7) + ((lane >> 4) << 3));
                uint32_t off = SWZ128(vrow * 128 + f * 32 + (((lane >> 3) & 1) << 4));
                LDSM_X4(bh,  vhbase + off);
                LDSM_X4(bm2, vmbase + off);
                MMA16816(O[2 * g],     ah[f], bh[0],  bh[1]);
                MMA16816(O[2 * g + 1], ah[f], bh[2],  bh[3]);
                MMA16816(O[2 * g],     am[f], bh[0],  bh[1]);
                MMA16816(O[2 * g + 1], am[f], bh[2],  bh[3]);
                MMA16816(O[2 * g],     ah[f], bm2[0], bm2[1]);
                MMA16816(O[2 * g + 1], ah[f], bm2[2], bm2[3]);
            }
        }

        __syncthreads();
        if (i + 2 < NB) {
            load_kv(kb0 + (i + 2) * 64, st);
        }
        asm volatile("cp.async.commit_group;" ::: "memory");
    }

    // ---- epilogue ----
    float invl0 = 1.0f / l0;
    float invl1 = 1.0f / l1;
    #pragma unroll
    for (int nt = 0; nt < 16; nt++) {
        int col = nt * 8 + (lane & 3) * 2;
        float* d0 = o + ((size_t)(b * T_SEQ + r0g) * H_Q + h) * D_HEAD + col;
        float* d1 = o + ((size_t)(b * T_SEQ + r1g) * H_Q + h) * D_HEAD + col;
        *(float2*)d0 = make_float2(O[nt][0] * invl0, O[nt][1] * invl0);
        *(float2*)d1 = make_float2(O[nt][2] * invl1, O[nt][3] * invl1);
    }
}

// ---------------------------------------------------------------------------
// launch
// ---------------------------------------------------------------------------
extern "C" void kernel_launch(void* const* d_in, const int* in_sizes, int n_in,
                              void* d_out, int out_size)
{
    const float* x  = (const float*)d_in[0];
    const float* Wq = (const float*)d_in[1];
    const float* Wk = (const float*)d_in[2];
    const float* Wv = (const float*)d_in[3];
    const float* Wo = (const float*)d_in[4];
    float* out = (float*)d_out;

    float *q, *k, *v, *att;
    cudaGetSymbolAddress((void**)&q,   g_q);
    cudaGetSymbolAddress((void**)&k,   g_k);
    cudaGetSymbolAddress((void**)&v,   g_v);
    cudaGetSymbolAddress((void**)&att, g_att);

    __nv_bfloat16 *xh, *xm, *wqh, *wqm, *wkh, *wkm, *wvh, *wvm, *woh, *wom, *ah, *am;
    __nv_bfloat16 *qbf, *kbf, *vth, *vtm;
    cudaGetSymbolAddress((void**)&xh,  g_xh);  cudaGetSymbolAddress((void**)&xm,  g_xm);
    cudaGetSymbolAddress((void**)&wqh, g_wqh); cudaGetSymbolAddress((void**)&wqm, g_wqm);
    cudaGetSymbolAddress((void**)&wkh, g_wkh); cudaGetSymbolAddress((void**)&wkm, g_wkm);
    cudaGetSymbolAddress((void**)&wvh, g_wvh); cudaGetSymbolAddress((void**)&wvm, g_wvm);
    cudaGetSymbolAddress((void**)&woh, g_woh); cudaGetSymbolAddress((void**)&wom, g_wom);
    cudaGetSymbolAddress((void**)&ah,  g_ah);  cudaGetSymbolAddress((void**)&am,  g_am);
    cudaGetSymbolAddress((void**)&qbf, g_qbf); cudaGetSymbolAddress((void**)&kbf, g_kbf);
    cudaGetSymbolAddress((void**)&vth, g_vth); cudaGetSymbolAddress((void**)&vtm, g_vtm);

    cudaFuncSetAttribute(tc_gemm, cudaFuncAttributeMaxDynamicSharedMemorySize, GK_SMEM);
    cudaFuncSetAttribute(attn_mma_kernel, cudaFuncAttributeMaxDynamicSharedMemorySize, AT_SMEM);

    rope_table_kernel<<<(T_SEQ * 64 + 255) / 256, 256>>>();

    int nx = M_ROWS * E_DIM;
    int nq = H_Q * D_HEAD * E_DIM;
    int nk = H_KV * D_HEAD * E_DIM;
    split_bf16_kernel<<<(nx / 4 + 255) / 256, 256>>>(x,  xh,  xm,  nx);
    split_bf16_kernel<<<(nq / 4 + 255) / 256, 256>>>(Wq, wqh, wqm, nq);
    split_bf16_kernel<<<(nk / 4 + 255) / 256, 256>>>(Wk, wkh, wkm, nk);
    split_bf16_kernel<<<(nk / 4 + 255) / 256, 256>>>(Wv, wvh, wvm, nk);
    split_bf16_kernel<<<(nq / 4 + 255) / 256, 256>>>(Wo, woh, wom, nq);

    tc_gemm<<<dim3(E_DIM / 128, M_ROWS / 128), 256, GK_SMEM>>>(
        xh, xm, wqh, wqm, q, M_ROWS, H_Q * D_HEAD, E_DIM);
    tc_gemm<<<dim3((H_KV * D_HEAD) / 128, M_ROWS / 128), 256, GK_SMEM>>>(
        xh, xm, wkh, wkm, k, M_ROWS, H_KV * D_HEAD, E_DIM);
    tc_gemm<<<dim3((H_KV * D_HEAD) / 128, M_ROWS / 128), 256, GK_SMEM>>>(
        xh, xm, wvh, wvm, v, M_ROWS, H_KV * D_HEAD, E_DIM);

    // pack attention operands (RoPE fused into Q/K pack)
    pack_q_kernel<<<(B_SZ * T_SEQ * H_Q  * 64) / 256, 256>>>(q, qbf);
    pack_k_kernel<<<(B_SZ * T_SEQ * H_KV * 64) / 256, 256>>>(k, kbf);
    pack_v_kernel<<<dim3(T_SEQ / 64, D_HEAD / 64, B_SZ * H_KV), 256>>>(v, vth, vtm);

    attn_mma_kernel<<<dim3(T_SEQ / 64, H_Q, B_SZ), 128, AT_SMEM>>>(qbf, kbf, vth, vtm, att);

    split_bf16_kernel<<<(nx / 4 + 255) / 256, 256>>>(att, ah, am, nx);
    tc_gemm<<<dim3(E_DIM / 128, M_ROWS / 128), 256, GK_SMEM>>>(
        ah, am, woh, wom, out, M_ROWS, E_DIM, E_DIM);
}

// round 6
// speedup vs baseline: 5.4933x; 1.1041x over previous
#include <cuda_runtime.h>
#include <cuda_fp16.h>
#include <cuda_bf16.h>
#include <math.h>
#include <stdint.h>

// Problem constants
#define T_SEQ   2048
#define B_SZ    2
#define E_DIM   2048
#define H_Q     16
#define H_KV    4
#define D_HEAD  128
#define M_ROWS  4096        // B*T
#define WIN     512

// ---------------------------------------------------------------------------
// Scratch (device globals: allocation-free rule)
// ---------------------------------------------------------------------------
__device__ float g_q  [M_ROWS * (H_Q  * D_HEAD)];
__device__ float g_k  [M_ROWS * (H_KV * D_HEAD)];
__device__ float g_v  [M_ROWS * (H_KV * D_HEAD)];
__device__ float g_att[M_ROWS * (H_Q  * D_HEAD)];
__device__ float g_cos[T_SEQ * 64];
__device__ float g_sin[T_SEQ * 64];

// fp16 GEMM operands (single-pass precision)
__device__ __half g_x16 [M_ROWS * E_DIM];
__device__ __half g_wq16[(H_Q  * D_HEAD) * E_DIM];
__device__ __half g_wk16[(H_KV * D_HEAD) * E_DIM];
__device__ __half g_wv16[(H_KV * D_HEAD) * E_DIM];
__device__ __half g_wo16[E_DIM * E_DIM];
__device__ __half g_a16 [M_ROWS * E_DIM];

// attention operands, head-major bf16 (validated path)
__device__ __nv_bfloat16 g_qbf[B_SZ * H_Q  * T_SEQ * D_HEAD];  // [b][h][t][d], RoPE'd
__device__ __nv_bfloat16 g_kbf[B_SZ * H_KV * T_SEQ * D_HEAD];  // [b][kv][t][d], RoPE'd
__device__ __nv_bfloat16 g_vth[B_SZ * H_KV * D_HEAD * T_SEQ];  // [b][kv][d][t] hi
__device__ __nv_bfloat16 g_vtm[B_SZ * H_KV * D_HEAD * T_SEQ];  // [b][kv][d][t] mid

// ---------------------------------------------------------------------------
// fp32 -> fp16 convert
// ---------------------------------------------------------------------------
__global__ void conv_fp16_kernel(const float* __restrict__ src,
                                 __half* __restrict__ dst, int n)
{
    int i = (blockIdx.x * 256 + threadIdx.x) * 4;
    if (i >= n) return;
    float4 v = *(const float4*)(src + i);
    __half2 lo = __floats2half2_rn(v.x, v.y);
    __half2 hi = __floats2half2_rn(v.z, v.w);
    uint2 pk;
    pk.x = *(uint32_t*)&lo;
    pk.y = *(uint32_t*)&hi;
    *(uint2*)(dst + i) = pk;
}

// ---------------------------------------------------------------------------
// RoPE tables
// ---------------------------------------------------------------------------
__global__ void rope_table_kernel() {
    int idx = blockIdx.x * 256 + threadIdx.x;
    if (idx >= T_SEQ * 64) return;
    int i = idx & 63;
    int t = idx >> 6;
    float ex = (float)(2 * i) * (1.0f / 128.0f);
    float invf = (float)(1.0 / pow(10000.0, (double)ex));
    float ang = (float)t * invf;
    double s, c;
    sincos((double)ang, &s, &c);
    g_cos[idx] = (float)c;
    g_sin[idx] = (float)s;
}

// ---------------------------------------------------------------------------
// Pack Q: fp32 [t][h][d] -> RoPE -> bf16 [b][h][t][d]
// ---------------------------------------------------------------------------
__global__ void pack_q_kernel(const float* __restrict__ q, __nv_bfloat16* __restrict__ o) {
    int idx = blockIdx.x * 256 + threadIdx.x;        // B*T*H*64
    int i = idx & 63;
    int h = (idx >> 6) & 15;
    int t = (idx >> 10) & 2047;
    int b = idx >> 21;
    float c = g_cos[t * 64 + i];
    float s = g_sin[t * 64 + i];
    const float* p = q + ((size_t)((b * T_SEQ + t) * H_Q + h)) * D_HEAD + i;
    float x1 = p[0], x2 = p[64];
    __nv_bfloat16* d = o + ((size_t)(b * H_Q + h) * T_SEQ + t) * D_HEAD + i;
    d[0]  = __float2bfloat16(x1 * c - x2 * s);
    d[64] = __float2bfloat16(x2 * c + x1 * s);
}

// Pack K: fp32 [t][kv][d] -> RoPE -> bf16 [b][kv][t][d]
__global__ void pack_k_kernel(const float* __restrict__ k, __nv_bfloat16* __restrict__ o) {
    int idx = blockIdx.x * 256 + threadIdx.x;        // B*T*KV*64
    int i = idx & 63;
    int kv = (idx >> 6) & 3;
    int t = (idx >> 8) & 2047;
    int b = idx >> 19;
    float c = g_cos[t * 64 + i];
    float s = g_sin[t * 64 + i];
    const float* p = k + ((size_t)((b * T_SEQ + t) * H_KV + kv)) * D_HEAD + i;
    float x1 = p[0], x2 = p[64];
    __nv_bfloat16* d = o + ((size_t)(b * H_KV + kv) * T_SEQ + t) * D_HEAD + i;
    d[0]  = __float2bfloat16(x1 * c - x2 * s);
    d[64] = __float2bfloat16(x2 * c + x1 * s);
}

// Pack V: fp32 [t][kv][d] -> transpose+split -> bf16 hi/mid [b][kv][d][t]
__global__ void pack_v_kernel(const float* __restrict__ v,
                              __nv_bfloat16* __restrict__ vth,
                              __nv_bfloat16* __restrict__ vtm)
{
    __shared__ float tile[64][65];
    int t0 = blockIdx.x * 64;
    int d0 = blockIdx.y * 64;
    int bk = blockIdx.z;             // b*4 + kv
    int b = bk >> 2, kv = bk & 3;
    int tr = threadIdx.x >> 4;
    int c4 = (threadIdx.x & 15) * 4;
    #pragma unroll
    for (int r = 0; r < 4; r++) {
        int t = t0 + tr + r * 16;
        float4 val = *(const float4*)&v[((size_t)(b * T_SEQ + t) * H_KV + kv) * D_HEAD + d0 + c4];
        tile[tr + r * 16][c4 + 0] = val.x;
        tile[tr + r * 16][c4 + 1] = val.y;
        tile[tr + r * 16][c4 + 2] = val.z;
        tile[tr + r * 16][c4 + 3] = val.w;
    }
    __syncthreads();
    int dr = threadIdx.x >> 2;
    int cg = (threadIdx.x & 3) * 16;
    size_t obase = ((size_t)bk * D_HEAD + d0 + dr) * T_SEQ + t0 + cg;
    #pragma unroll
    for (int j = 0; j < 16; j++) {
        float x = tile[cg + j][dr];
        __nv_bfloat16 h = __float2bfloat16(x);
        vth[obase + j] = h;
        vtm[obase + j] = __float2bfloat16(x - __bfloat162float(h));
    }
}

// ---------------------------------------------------------------------------
// Single-pass fp16 GEMM (NT): C[M,N] = A[M,K] * B[N,K]^T, fp32 accumulate.
// Tile 128x128, K-chunk 64 (128B SW128 rows), 3-stage cp.async ring.
// mma.sync m16n8k16 f16 (fragment layout identical to validated bf16 path).
// ---------------------------------------------------------------------------
#define GK_BK        64
#define GK_TILE_B    16384
#define GK_STAGE_B   32768          // A + B tiles
#define GK_SMEM      (1024 + 3 * GK_STAGE_B)

#define SWZ128(o) ((o) ^ (((o) >> 3) & 0x70))

static __device__ __forceinline__ uint32_t s2u(const void* p) {
    uint32_t a;
    asm("{ .reg .u64 t; cvta.to.shared.u64 t, %1; cvt.u32.u64 %0, t; }" : "=r"(a) : "l"(p));
    return a;
}

#define LDSM_X4(r, addr)                                                      \
    asm volatile("ldmatrix.sync.aligned.m8n8.x4.shared.b16 {%0,%1,%2,%3}, [%4];" \
        : "=r"((r)[0]), "=r"((r)[1]), "=r"((r)[2]), "=r"((r)[3]) : "r"(addr))

#define MMA16816F(d, a, b0, b1)                                               \
    asm volatile("mma.sync.aligned.m16n8k16.row.col.f32.f16.f16.f32 "         \
        "{%0,%1,%2,%3}, {%4,%5,%6,%7}, {%8,%9}, {%0,%1,%2,%3};"               \
        : "+f"((d)[0]), "+f"((d)[1]), "+f"((d)[2]), "+f"((d)[3])              \
        : "r"((a)[0]), "r"((a)[1]), "r"((a)[2]), "r"((a)[3]),                 \
          "r"(b0), "r"(b1))

#define MMA16816B(d, a, b0, b1)                                               \
    asm volatile("mma.sync.aligned.m16n8k16.row.col.f32.bf16.bf16.f32 "       \
        "{%0,%1,%2,%3}, {%4,%5,%6,%7}, {%8,%9}, {%0,%1,%2,%3};"               \
        : "+f"((d)[0]), "+f"((d)[1]), "+f"((d)[2]), "+f"((d)[3])              \
        : "r"((a)[0]), "r"((a)[1]), "r"((a)[2]), "r"((a)[3]),                 \
          "r"(b0), "r"(b1))

__global__ void __launch_bounds__(256)
h_gemm(const __half* __restrict__ A, const __half* __restrict__ B,
       float* __restrict__ C, int M, int N, int K)
{
    extern __shared__ char smem_raw[];
    uint32_t sbase  = (s2u(smem_raw) + 1023) & ~1023u;
    uint32_t stages = sbase;

    const int tid  = threadIdx.x;
    const int wid  = tid >> 5;
    const int lane = tid & 31;
    const int bm = blockIdx.y * 128;
    const int bn = blockIdx.x * 128;
    const int NC = K / GK_BK;

    const char* gA = (const char*)(A + (size_t)bm * K);
    const char* gB = (const char*)(B + (size_t)bn * K);

    const int rowK2 = K * 2;
    const int r0    = tid >> 3;          // 0..31
    const int c16   = (tid & 7) * 16;

    auto load_chunk = [&](int c, int st) {
        uint32_t sbs = stages + st * GK_STAGE_B;
        long koff = (long)c * GK_BK * 2;
        #pragma unroll
        for (int r = 0; r < 4; r++) {
            int row = r0 + r * 32;
            uint32_t dst = sbs + SWZ128(row * 128 + c16);
            asm volatile("cp.async.cg.shared.global [%0], [%1], 16;"
                         :: "r"(dst), "l"(gA + (size_t)row * rowK2 + koff + c16) : "memory");
            asm volatile("cp.async.cg.shared.global [%0], [%1], 16;"
                         :: "r"(dst + GK_TILE_B), "l"(gB + (size_t)row * rowK2 + koff + c16) : "memory");
        }
    };

    const int wm = wid >> 2;
    const int wn = wid & 3;

    float acc[4][4][4];
    #pragma unroll
    for (int mt = 0; mt < 4; mt++)
        #pragma unroll
        for (int nt = 0; nt < 4; nt++)
            #pragma unroll
            for (int e = 0; e < 4; e++) acc[mt][nt][e] = 0.0f;

    #pragma unroll
    for (int p = 0; p < 3; p++) {
        load_chunk(p, p);
        asm volatile("cp.async.commit_group;" ::: "memory");
    }

    const int a_row  = wm * 64 + (lane & 15);
    const int a_byte = (lane >> 4) * 16;
    const int b_row  = wn * 32 + (lane & 7) + ((lane >> 4) << 3);
    const int b_byte = ((lane >> 3) & 1) << 4;

    for (int c = 0; c < NC; c++) {
        int st = c % 3;
        asm volatile("cp.async.wait_group 2;" ::: "memory");
        __syncthreads();

        uint32_t tA = stages + st * GK_STAGE_B;
        uint32_t tB = tA + GK_TILE_B;

        #pragma unroll
        for (int ks = 0; ks < 4; ks++) {
            const int kb = ks * 32;
            uint32_t a_f[4][4], b_f[2][4];
            #pragma unroll
            for (int mt = 0; mt < 4; mt++) {
                uint32_t off = SWZ128((a_row + mt * 16) * 128 + kb + a_byte);
                LDSM_X4(a_f[mt], tA + off);
            }
            #pragma unroll
            for (int g = 0; g < 2; g++) {
                uint32_t off = SWZ128((b_row + g * 16) * 128 + kb + b_byte);
                LDSM_X4(b_f[g], tB + off);
            }
            #pragma unroll
            for (int mt = 0; mt < 4; mt++) {
                #pragma unroll
                for (int nt = 0; nt < 4; nt++) {
                    const int g = nt >> 1;
                    const int o = (nt & 1) * 2;
                    MMA16816F(acc[mt][nt], a_f[mt], b_f[g][o], b_f[g][o + 1]);
                }
            }
        }
        __syncthreads();
        if (c + 3 < NC) load_chunk(c + 3, st);
        asm volatile("cp.async.commit_group;" ::: "memory");
    }

    #pragma unroll
    for (int mt = 0; mt < 4; mt++) {
        #pragma unroll
        for (int nt = 0; nt < 4; nt++) {
            int rr = bm + wm * 64 + mt * 16 + (lane >> 2);
            int cc = bn + wn * 32 + nt * 8 + (lane & 3) * 2;
            *(float2*)(C + (size_t)rr * N + cc) =
                make_float2(acc[mt][nt][0], acc[mt][nt][1]);
            *(float2*)(C + (size_t)(rr + 8) * N + cc) =
                make_float2(acc[mt][nt][2], acc[mt][nt][3]);
        }
    }
}

// ---------------------------------------------------------------------------
// Tensor-core flash attention (validated in R5) — unchanged.
// ---------------------------------------------------------------------------
#define AT_Q_B     16384
#define AT_STG_B   49152            // K(16K) + Vh(16K) + Vm(16K)
#define AT_SMEM    (AT_Q_B + 2 * AT_STG_B)

static __device__ __forceinline__ void split2(float x, float y,
                                              uint32_t& hi, uint32_t& mi) {
    __nv_bfloat162 h;
    h.x = __float2bfloat16(x);
    h.y = __float2bfloat16(y);
    __nv_bfloat162 m;
    m.x = __float2bfloat16(x - __bfloat162float(h.x));
    m.y = __float2bfloat16(y - __bfloat162float(h.y));
    hi = *(uint32_t*)&h;
    mi = *(uint32_t*)&m;
}

__global__ void __launch_bounds__(128, 2) attn_mma_kernel(
    const __nv_bfloat16* __restrict__ qbf, const __nv_bfloat16* __restrict__ kbf,
    const __nv_bfloat16* __restrict__ vth, const __nv_bfloat16* __restrict__ vtm,
    float* __restrict__ o)
{
    extern __shared__ char smem_raw[];
    const uint32_t sb   = s2u(smem_raw);
    const int tid  = threadIdx.x;
    const int w    = tid >> 5;
    const int lane = tid & 31;
    const int qs   = blockIdx.x * 64;
    const int h    = blockIdx.y;
    const int b    = blockIdx.z;
    const int kvh  = h >> 2;
    const float scale = 0.08838834764831845f;

    const char* qb  = (const char*)(qbf + ((size_t)(b * H_Q + h) * T_SEQ + qs) * D_HEAD);
    const char* kb_ = (const char*)(kbf + (size_t)(b * H_KV + kvh) * T_SEQ * D_HEAD);
    const char* vhb = (const char*)(vth + (size_t)(b * H_KV + kvh) * D_HEAD * T_SEQ);
    const char* vmb = (const char*)(vtm + (size_t)(b * H_KV + kvh) * D_HEAD * T_SEQ);

    const int kb0 = (qs >= WIN) ? qs - WIN : 0;
    const int NB  = ((qs - kb0) >> 6) + 1;

    auto load_kv = [&](int kb, int st) {
        uint32_t base = sb + AT_Q_B + st * AT_STG_B;
        const char* ks = kb_ + (size_t)kb * 256;
        const char* vh = vhb + ((size_t)tid * T_SEQ + kb) * 2;
        const char* vm = vmb + ((size_t)tid * T_SEQ + kb) * 2;
        #pragma unroll
        for (int j = 0; j < 8; j++) {
            uint32_t off = SWZ128(tid * 128 + j * 16);
            asm volatile("cp.async.cg.shared.global [%0], [%1], 16;"
                         :: "r"(base + off), "l"(ks + tid * 128 + j * 16) : "memory");
            asm volatile("cp.async.cg.shared.global [%0], [%1], 16;"
                         :: "r"(base + 16384 + off), "l"(vh + j * 16) : "memory");
            asm volatile("cp.async.cg.shared.global [%0], [%1], 16;"
                         :: "r"(base + 32768 + off), "l"(vm + j * 16) : "memory");
        }
    };

    #pragma unroll
    for (int j = 0; j < 8; j++) {
        asm volatile("cp.async.cg.shared.global [%0], [%1], 16;"
                     :: "r"(sb + SWZ128(tid * 128 + j * 16)),
                        "l"(qb + tid * 128 + j * 16) : "memory");
    }
    load_kv(kb0, 0);
    asm volatile("cp.async.commit_group;" ::: "memory");
    if (NB > 1) {
        load_kv(kb0 + 64, 1);
        asm volatile("cp.async.commit_group;" ::: "memory");
    }

    float O[16][4];
    #pragma unroll
    for (int nt = 0; nt < 16; nt++)
        #pragma unroll
        for (int e = 0; e < 4; e++) O[nt][e] = 0.0f;
    float m0 = -1e30f, m1 = -1e30f, l0 = 0.0f, l1 = 0.0f;

    const int r0g = qs + w * 16 + (lane >> 2);
    const int r1g = r0g + 8;

    for (int i = 0; i < NB; i++) {
        const int kb = kb0 + i * 64;
        const int st = i & 1;
        if (i + 1 < NB) asm volatile("cp.async.wait_group 1;" ::: "memory");
        else            asm volatile("cp.async.wait_group 0;" ::: "memory");
        __syncthreads();

        const uint32_t kbase = sb + AT_Q_B + st * AT_STG_B;
        const uint32_t vhbase = kbase + 16384;
        const uint32_t vmbase = kbase + 32768;

        float sreg[8][4];
        #pragma unroll
        for (int t = 0; t < 8; t++)
            #pragma unroll
            for (int e = 0; e < 4; e++) sreg[t][e] = 0.0f;

        #pragma unroll
        for (int ks = 0; ks < 8; ks++) {
            const int khalf = ks >> 2;
            const int kb32  = (ks & 3) * 32;
            uint32_t a[4];
            {
                uint32_t vrow = (uint32_t)(w * 16 + (lane & 15)) * 2 + khalf;
                LDSM_X4(a, sb + SWZ128(vrow * 128 + kb32 + (lane >> 4) * 16));
            }
            #pragma unroll
            for (int g = 0; g < 4; g++) {
                uint32_t bf[4];
                uint32_t vrow = (uint32_t)(g * 16 + (lane & 7) + ((lane >> 4) << 3)) * 2 + khalf;
                LDSM_X4(bf, kbase + SWZ128(vrow * 128 + kb32 + (((lane >> 3) & 1) << 4)));
                MMA16816B(sreg[g * 2],     a, bf[0], bf[1]);
                MMA16816B(sreg[g * 2 + 1], a, bf[2], bf[3]);
            }
        }

        float mx0 = -1e30f, mx1 = -1e30f;
        #pragma unroll
        for (int t = 0; t < 8; t++) {
            int c0 = kb + t * 8 + (lane & 3) * 2;
            int c1 = c0 + 1;
            sreg[t][0] = (c0 <= r0g && r0g - c0 < WIN) ? sreg[t][0] * scale : -1e30f;
            sreg[t][1] = (c1 <= r0g && r0g - c1 < WIN) ? sreg[t][1] * scale : -1e30f;
            sreg[t][2] = (c0 <= r1g && r1g - c0 < WIN) ? sreg[t][2] * scale : -1e30f;
            sreg[t][3] = (c1 <= r1g && r1g - c1 < WIN) ? sreg[t][3] * scale : -1e30f;
            mx0 = fmaxf(mx0, fmaxf(sreg[t][0], sreg[t][1]));
            mx1 = fmaxf(mx1, fmaxf(sreg[t][2], sreg[t][3]));
        }
        mx0 = fmaxf(mx0, __shfl_xor_sync(0xffffffffu, mx0, 1));
        mx0 = fmaxf(mx0, __shfl_xor_sync(0xffffffffu, mx0, 2));
        mx1 = fmaxf(mx1, __shfl_xor_sync(0xffffffffu, mx1, 1));
        mx1 = fmaxf(mx1, __shfl_xor_sync(0xffffffffu, mx1, 2));

        float mn0 = fmaxf(m0, mx0), mn1 = fmaxf(m1, mx1);
        float corr0 = __expf(m0 - mn0), corr1 = __expf(m1 - mn1);
        m0 = mn0; m1 = mn1;

        float sum0 = 0.0f, sum1 = 0.0f;
        #pragma unroll
        for (int t = 0; t < 8; t++) {
            sreg[t][0] = __expf(sreg[t][0] - m0);
            sreg[t][1] = __expf(sreg[t][1] - m0);
            sreg[t][2] = __expf(sreg[t][2] - m1);
            sreg[t][3] = __expf(sreg[t][3] - m1);
            sum0 += sreg[t][0] + sreg[t][1];
            sum1 += sreg[t][2] + sreg[t][3];
        }
        sum0 += __shfl_xor_sync(0xffffffffu, sum0, 1);
        sum0 += __shfl_xor_sync(0xffffffffu, sum0, 2);
        sum1 += __shfl_xor_sync(0xffffffffu, sum1, 1);
        sum1 += __shfl_xor_sync(0xffffffffu, sum1, 2);
        l0 = l0 * corr0 + sum0;
        l1 = l1 * corr1 + sum1;

        #pragma unroll
        for (int nt = 0; nt < 16; nt++) {
            O[nt][0] *= corr0; O[nt][1] *= corr0;
            O[nt][2] *= corr1; O[nt][3] *= corr1;
        }

        uint32_t ah[4][4], am[4][4];
        #pragma unroll
        for (int f = 0; f < 4; f++) {
            split2(sreg[2 * f][0],     sreg[2 * f][1],     ah[f][0], am[f][0]);
            split2(sreg[2 * f][2],     sreg[2 * f][3],     ah[f][1], am[f][1]);
            split2(sreg[2 * f + 1][0], sreg[2 * f + 1][1], ah[f][2], am[f][2]);
            split2(sreg[2 * f + 1][2], sreg[2 * f + 1][3], ah[f][3], am[f][3]);
        }

        #pragma unroll
        for (int f = 0; f < 4; f++) {
            #pragma unroll
            for (int g = 0; g < 8; g++) {
                uint32_t bh[4], bm2[4];
                uint32_t vrow = (uint32_t)(g * 16 + (lane & 7) + ((lane >> 4) << 3));
                uint32_t off = SWZ128(vrow * 128 + f * 32 + (((lane >> 3) & 1) << 4));
                LDSM_X4(bh,  vhbase + off);
                LDSM_X4(bm2, vmbase + off);
                MMA16816B(O[2 * g],     ah[f], bh[0],  bh[1]);
                MMA16816B(O[2 * g + 1], ah[f], bh[2],  bh[3]);
                MMA16816B(O[2 * g],     am[f], bh[0],  bh[1]);
                MMA16816B(O[2 * g + 1], am[f], bh[2],  bh[3]);
                MMA16816B(O[2 * g],     ah[f], bm2[0], bm2[1]);
                MMA16816B(O[2 * g + 1], ah[f], bm2[2], bm2[3]);
            }
        }

        __syncthreads();
        if (i + 2 < NB) {
            load_kv(kb0 + (i + 2) * 64, st);
        }
        asm volatile("cp.async.commit_group;" ::: "memory");
    }

    float invl0 = 1.0f / l0;
    float invl1 = 1.0f / l1;
    #pragma unroll
    for (int nt = 0; nt < 16; nt++) {
        int col = nt * 8 + (lane & 3) * 2;
        float* d0 = o + ((size_t)(b * T_SEQ + r0g) * H_Q + h) * D_HEAD + col;
        float* d1 = o + ((size_t)(b * T_SEQ + r1g) * H_Q + h) * D_HEAD + col;
        *(float2*)d0 = make_float2(O[nt][0] * invl0, O[nt][1] * invl0);
        *(float2*)d1 = make_float2(O[nt][2] * invl1, O[nt][3] * invl1);
    }
}

// ---------------------------------------------------------------------------
// launch
// ---------------------------------------------------------------------------
extern "C" void kernel_launch(void* const* d_in, const int* in_sizes, int n_in,
                              void* d_out, int out_size)
{
    const float* x  = (const float*)d_in[0];
    const float* Wq = (const float*)d_in[1];
    const float* Wk = (const float*)d_in[2];
    const float* Wv = (const float*)d_in[3];
    const float* Wo = (const float*)d_in[4];
    float* out = (float*)d_out;

    float *q, *k, *v, *att;
    cudaGetSymbolAddress((void**)&q,   g_q);
    cudaGetSymbolAddress((void**)&k,   g_k);
    cudaGetSymbolAddress((void**)&v,   g_v);
    cudaGetSymbolAddress((void**)&att, g_att);

    __half *x16, *wq16, *wk16, *wv16, *wo16, *a16;
    cudaGetSymbolAddress((void**)&x16,  g_x16);
    cudaGetSymbolAddress((void**)&wq16, g_wq16);
    cudaGetSymbolAddress((void**)&wk16, g_wk16);
    cudaGetSymbolAddress((void**)&wv16, g_wv16);
    cudaGetSymbolAddress((void**)&wo16, g_wo16);
    cudaGetSymbolAddress((void**)&a16,  g_a16);

    __nv_bfloat16 *qbf, *kbf, *vth, *vtm;
    cudaGetSymbolAddress((void**)&qbf, g_qbf);
    cudaGetSymbolAddress((void**)&kbf, g_kbf);
    cudaGetSymbolAddress((void**)&vth, g_vth);
    cudaGetSymbolAddress((void**)&vtm, g_vtm);

    cudaFuncSetAttribute(h_gemm, cudaFuncAttributeMaxDynamicSharedMemorySize, GK_SMEM);
    cudaFuncSetAttribute(attn_mma_kernel, cudaFuncAttributeMaxDynamicSharedMemorySize, AT_SMEM);

    rope_table_kernel<<<(T_SEQ * 64 + 255) / 256, 256>>>();

    int nx = M_ROWS * E_DIM;
    int nq = H_Q * D_HEAD * E_DIM;
    int nk = H_KV * D_HEAD * E_DIM;
    conv_fp16_kernel<<<(nx / 4 + 255) / 256, 256>>>(x,  x16,  nx);
    conv_fp16_kernel<<<(nq / 4 + 255) / 256, 256>>>(Wq, wq16, nq);
    conv_fp16_kernel<<<(nk / 4 + 255) / 256, 256>>>(Wk, wk16, nk);
    conv_fp16_kernel<<<(nk / 4 + 255) / 256, 256>>>(Wv, wv16, nk);
    conv_fp16_kernel<<<(nq / 4 + 255) / 256, 256>>>(Wo, wo16, nq);

    h_gemm<<<dim3(E_DIM / 128, M_ROWS / 128), 256, GK_SMEM>>>(
        x16, wq16, q, M_ROWS, H_Q * D_HEAD, E_DIM);
    h_gemm<<<dim3((H_KV * D_HEAD) / 128, M_ROWS / 128), 256, GK_SMEM>>>(
        x16, wk16, k, M_ROWS, H_KV * D_HEAD, E_DIM);
    h_gemm<<<dim3((H_KV * D_HEAD) / 128, M_ROWS / 128), 256, GK_SMEM>>>(
        x16, wv16, v, M_ROWS, H_KV * D_HEAD, E_DIM);

    pack_q_kernel<<<(B_SZ * T_SEQ * H_Q  * 64) / 256, 256>>>(q, qbf);
    pack_k_kernel<<<(B_SZ * T_SEQ * H_KV * 64) / 256, 256>>>(k, kbf);
    pack_v_kernel<<<dim3(T_SEQ / 64, D_HEAD / 64, B_SZ * H_KV), 256>>>(v, vth, vtm);

    attn_mma_kernel<<<dim3(T_SEQ / 64, H_Q, B_SZ), 128, AT_SMEM>>>(qbf, kbf, vth, vtm, att);

    conv_fp16_kernel<<<(nx / 4 + 255) / 256, 256>>>(att, a16, nx);
    h_gemm<<<dim3(E_DIM / 128, M_ROWS / 128), 256, GK_SMEM>>>(
        a16, wo16, out, M_ROWS, E_DIM, E_DIM);
}

// round 7
// speedup vs baseline: 6.2264x; 1.1335x over previous
#include <cuda_runtime.h>
#include <cuda_fp16.h>
#include <math.h>
#include <stdint.h>

// Problem constants
#define T_SEQ   2048
#define B_SZ    2
#define E_DIM   2048
#define H_Q     16
#define H_KV    4
#define D_HEAD  128
#define M_ROWS  4096        // B*T
#define WIN     512

// ---------------------------------------------------------------------------
// Scratch (device globals: allocation-free rule)
// ---------------------------------------------------------------------------
__device__ float g_q  [M_ROWS * (H_Q  * D_HEAD)];
__device__ float g_k  [M_ROWS * (H_KV * D_HEAD)];
__device__ float g_v  [M_ROWS * (H_KV * D_HEAD)];
__device__ float g_att[M_ROWS * (H_Q  * D_HEAD)];
__device__ float g_cos[T_SEQ * 64];
__device__ float g_sin[T_SEQ * 64];

// fp16 GEMM operands
__device__ __half g_x16 [M_ROWS * E_DIM];
__device__ __half g_wq16[(H_Q  * D_HEAD) * E_DIM];
__device__ __half g_wk16[(H_KV * D_HEAD) * E_DIM];
__device__ __half g_wv16[(H_KV * D_HEAD) * E_DIM];
__device__ __half g_wo16[E_DIM * E_DIM];
__device__ __half g_a16 [M_ROWS * E_DIM];

// attention operands, head-major fp16
__device__ __half g_q16p[B_SZ * H_Q  * T_SEQ * D_HEAD];  // [b][h][t][d], RoPE'd
__device__ __half g_k16p[B_SZ * H_KV * T_SEQ * D_HEAD];  // [b][kv][t][d], RoPE'd
__device__ __half g_vt16[B_SZ * H_KV * D_HEAD * T_SEQ];  // [b][kv][d][t]

// ---------------------------------------------------------------------------
// fp32 -> fp16 convert
// ---------------------------------------------------------------------------
__global__ void conv_fp16_kernel(const float* __restrict__ src,
                                 __half* __restrict__ dst, int n)
{
    int i = (blockIdx.x * 256 + threadIdx.x) * 4;
    if (i >= n) return;
    float4 v = *(const float4*)(src + i);
    __half2 lo = __floats2half2_rn(v.x, v.y);
    __half2 hi = __floats2half2_rn(v.z, v.w);
    uint2 pk;
    pk.x = *(uint32_t*)&lo;
    pk.y = *(uint32_t*)&hi;
    *(uint2*)(dst + i) = pk;
}

// ---------------------------------------------------------------------------
// RoPE tables
// ---------------------------------------------------------------------------
__global__ void rope_table_kernel() {
    int idx = blockIdx.x * 256 + threadIdx.x;
    if (idx >= T_SEQ * 64) return;
    int i = idx & 63;
    int t = idx >> 6;
    float ex = (float)(2 * i) * (1.0f / 128.0f);
    float invf = (float)(1.0 / pow(10000.0, (double)ex));
    float ang = (float)t * invf;
    double s, c;
    sincos((double)ang, &s, &c);
    g_cos[idx] = (float)c;
    g_sin[idx] = (float)s;
}

// ---------------------------------------------------------------------------
// Pack Q: fp32 [t][h][d] -> RoPE -> fp16 [b][h][t][d]
// ---------------------------------------------------------------------------
__global__ void pack_q_kernel(const float* __restrict__ q, __half* __restrict__ o) {
    int idx = blockIdx.x * 256 + threadIdx.x;
    int i = idx & 63;
    int h = (idx >> 6) & 15;
    int t = (idx >> 10) & 2047;
    int b = idx >> 21;
    float c = g_cos[t * 64 + i];
    float s = g_sin[t * 64 + i];
    const float* p = q + ((size_t)((b * T_SEQ + t) * H_Q + h)) * D_HEAD + i;
    float x1 = p[0], x2 = p[64];
    __half* d = o + ((size_t)(b * H_Q + h) * T_SEQ + t) * D_HEAD + i;
    d[0]  = __float2half(x1 * c - x2 * s);
    d[64] = __float2half(x2 * c + x1 * s);
}

// Pack K: fp32 [t][kv][d] -> RoPE -> fp16 [b][kv][t][d]
__global__ void pack_k_kernel(const float* __restrict__ k, __half* __restrict__ o) {
    int idx = blockIdx.x * 256 + threadIdx.x;
    int i = idx & 63;
    int kv = (idx >> 6) & 3;
    int t = (idx >> 8) & 2047;
    int b = idx >> 19;
    float c = g_cos[t * 64 + i];
    float s = g_sin[t * 64 + i];
    const float* p = k + ((size_t)((b * T_SEQ + t) * H_KV + kv)) * D_HEAD + i;
    float x1 = p[0], x2 = p[64];
    __half* d = o + ((size_t)(b * H_KV + kv) * T_SEQ + t) * D_HEAD + i;
    d[0]  = __float2half(x1 * c - x2 * s);
    d[64] = __float2half(x2 * c + x1 * s);
}

// Pack V: fp32 [t][kv][d] -> transpose -> fp16 [b][kv][d][t]
__global__ void pack_v_kernel(const float* __restrict__ v, __half* __restrict__ vt)
{
    __shared__ float tile[64][65];
    int t0 = blockIdx.x * 64;
    int d0 = blockIdx.y * 64;
    int bk = blockIdx.z;             // b*4 + kv
    int b = bk >> 2, kv = bk & 3;
    int tr = threadIdx.x >> 4;
    int c4 = (threadIdx.x & 15) * 4;
    #pragma unroll
    for (int r = 0; r < 4; r++) {
        int t = t0 + tr + r * 16;
        float4 val = *(const float4*)&v[((size_t)(b * T_SEQ + t) * H_KV + kv) * D_HEAD + d0 + c4];
        tile[tr + r * 16][c4 + 0] = val.x;
        tile[tr + r * 16][c4 + 1] = val.y;
        tile[tr + r * 16][c4 + 2] = val.z;
        tile[tr + r * 16][c4 + 3] = val.w;
    }
    __syncthreads();
    int dr = threadIdx.x >> 2;
    int cg = (threadIdx.x & 3) * 16;
    size_t obase = ((size_t)bk * D_HEAD + d0 + dr) * T_SEQ + t0 + cg;
    #pragma unroll
    for (int j = 0; j < 16; j++)
        vt[obase + j] = __float2half(tile[cg + j][dr]);
}

// ---------------------------------------------------------------------------
// fp16 GEMM core (NT), 128x128 tile, 3-stage cp.async, mma m16n8k16
// ---------------------------------------------------------------------------
#define GK_BK        64
#define GK_TILE_B    16384
#define GK_STAGE_B   32768
#define GK_SMEM      (1024 + 3 * GK_STAGE_B)

#define SWZ128(o) ((o) ^ (((o) >> 3) & 0x70))

static __device__ __forceinline__ uint32_t s2u(const void* p) {
    uint32_t a;
    asm("{ .reg .u64 t; cvta.to.shared.u64 t, %1; cvt.u32.u64 %0, t; }" : "=r"(a) : "l"(p));
    return a;
}

#define LDSM_X4(r, addr)                                                      \
    asm volatile("ldmatrix.sync.aligned.m8n8.x4.shared.b16 {%0,%1,%2,%3}, [%4];" \
        : "=r"((r)[0]), "=r"((r)[1]), "=r"((r)[2]), "=r"((r)[3]) : "r"(addr))

#define MMA16816F(d, a, b0, b1)                                               \
    asm volatile("mma.sync.aligned.m16n8k16.row.col.f32.f16.f16.f32 "         \
        "{%0,%1,%2,%3}, {%4,%5,%6,%7}, {%8,%9}, {%0,%1,%2,%3};"               \
        : "+f"((d)[0]), "+f"((d)[1]), "+f"((d)[2]), "+f"((d)[3])              \
        : "r"((a)[0]), "r"((a)[1]), "r"((a)[2]), "r"((a)[3]),                 \
          "r"(b0), "r"(b1))

static __device__ __forceinline__ void gemm_body(
    const __half* A, const __half* B, float* C,
    int bm, int bn, int N, int K, uint32_t stages)
{
    const int tid  = threadIdx.x;
    const int wid  = tid >> 5;
    const int lane = tid & 31;
    const int NC = K / GK_BK;

    const char* gA = (const char*)(A + (size_t)bm * K);
    const char* gB = (const char*)(B + (size_t)bn * K);

    const int rowK2 = K * 2;
    const int r0    = tid >> 3;
    const int c16   = (tid & 7) * 16;

    auto load_chunk = [&](int c, int st) {
        uint32_t sbs = stages + st * GK_STAGE_B;
        long koff = (long)c * GK_BK * 2;
        #pragma unroll
        for (int r = 0; r < 4; r++) {
            int row = r0 + r * 32;
            uint32_t dst = sbs + SWZ128(row * 128 + c16);
            asm volatile("cp.async.cg.shared.global [%0], [%1], 16;"
                         :: "r"(dst), "l"(gA + (size_t)row * rowK2 + koff + c16) : "memory");
            asm volatile("cp.async.cg.shared.global [%0], [%1], 16;"
                         :: "r"(dst + GK_TILE_B), "l"(gB + (size_t)row * rowK2 + koff + c16) : "memory");
        }
    };

    const int wm = wid >> 2;
    const int wn = wid & 3;

    float acc[4][4][4];
    #pragma unroll
    for (int mt = 0; mt < 4; mt++)
        #pragma unroll
        for (int nt = 0; nt < 4; nt++)
            #pragma unroll
            for (int e = 0; e < 4; e++) acc[mt][nt][e] = 0.0f;

    #pragma unroll
    for (int p = 0; p < 3; p++) {
        load_chunk(p, p);
        asm volatile("cp.async.commit_group;" ::: "memory");
    }

    const int a_row  = wm * 64 + (lane & 15);
    const int a_byte = (lane >> 4) * 16;
    const int b_row  = wn * 32 + (lane & 7) + ((lane >> 4) << 3);
    const int b_byte = ((lane >> 3) & 1) << 4;

    for (int c = 0; c < NC; c++) {
        int st = c % 3;
        asm volatile("cp.async.wait_group 2;" ::: "memory");
        __syncthreads();

        uint32_t tA = stages + st * GK_STAGE_B;
        uint32_t tB = tA + GK_TILE_B;

        #pragma unroll
        for (int ks = 0; ks < 4; ks++) {
            const int kb = ks * 32;
            uint32_t a_f[4][4], b_f[2][4];
            #pragma unroll
            for (int mt = 0; mt < 4; mt++) {
                uint32_t off = SWZ128((a_row + mt * 16) * 128 + kb + a_byte);
                LDSM_X4(a_f[mt], tA + off);
            }
            #pragma unroll
            for (int g = 0; g < 2; g++) {
                uint32_t off = SWZ128((b_row + g * 16) * 128 + kb + b_byte);
                LDSM_X4(b_f[g], tB + off);
            }
            #pragma unroll
            for (int mt = 0; mt < 4; mt++) {
                #pragma unroll
                for (int nt = 0; nt < 4; nt++) {
                    const int g = nt >> 1;
                    const int o = (nt & 1) * 2;
                    MMA16816F(acc[mt][nt], a_f[mt], b_f[g][o], b_f[g][o + 1]);
                }
            }
        }
        __syncthreads();
        if (c + 3 < NC) load_chunk(c + 3, st);
        asm volatile("cp.async.commit_group;" ::: "memory");
    }

    #pragma unroll
    for (int mt = 0; mt < 4; mt++) {
        #pragma unroll
        for (int nt = 0; nt < 4; nt++) {
            int rr = bm + wm * 64 + mt * 16 + (lane >> 2);
            int cc = bn + wn * 32 + nt * 8 + (lane & 3) * 2;
            *(float2*)(C + (size_t)rr * N + cc) =
                make_float2(acc[mt][nt][0], acc[mt][nt][1]);
            *(float2*)(C + (size_t)(rr + 8) * N + cc) =
                make_float2(acc[mt][nt][2], acc[mt][nt][3]);
        }
    }
}

// fused QKV projection: grid (24, 32). bx<16 -> Q, 16..19 -> K, 20..23 -> V
__global__ void __launch_bounds__(256)
qkv_gemm(const __half* __restrict__ X,
         const __half* __restrict__ Wq, const __half* __restrict__ Wk,
         const __half* __restrict__ Wv,
         float* __restrict__ q, float* __restrict__ k, float* __restrict__ v)
{
    extern __shared__ char smem_raw[];
    uint32_t stages = (s2u(smem_raw) + 1023) & ~1023u;
    int bx = blockIdx.x;
    int bm = blockIdx.y * 128;
    const __half* B;
    float* C;
    int N, bn;
    if (bx < 16)      { B = Wq; C = q; N = 2048; bn = bx * 128; }
    else if (bx < 20) { B = Wk; C = k; N = 512;  bn = (bx - 16) * 128; }
    else              { B = Wv; C = v; N = 512;  bn = (bx - 20) * 128; }
    gemm_body(X, B, C, bm, bn, N, E_DIM, stages);
}

// plain GEMM (output projection)
__global__ void __launch_bounds__(256)
h_gemm(const __half* __restrict__ A, const __half* __restrict__ B,
       float* __restrict__ C, int M, int N, int K)
{
    extern __shared__ char smem_raw[];
    uint32_t stages = (s2u(smem_raw) + 1023) & ~1023u;
    gemm_body(A, B, C, blockIdx.y * 128, blockIdx.x * 128, N, K, stages);
}

// ---------------------------------------------------------------------------
// fp16 flash attention: 256 threads, 128 queries/CTA, single-pass PV.
// smem: Q 32KB + 2 stages x (K 16KB + V 16KB) = 96KB
// ---------------------------------------------------------------------------
#define AT_Q_B     32768
#define AT_STG_B   32768
#define AT_SMEM    (AT_Q_B + 2 * AT_STG_B)

__global__ void __launch_bounds__(256, 2) attn_mma_kernel(
    const __half* __restrict__ q16, const __half* __restrict__ k16,
    const __half* __restrict__ vt16, float* __restrict__ o)
{
    extern __shared__ char smem_raw[];
    const uint32_t sb   = s2u(smem_raw);
    const int tid  = threadIdx.x;
    const int w    = tid >> 5;
    const int lane = tid & 31;
    const int qs   = blockIdx.x * 128;
    const int h    = blockIdx.y;
    const int b    = blockIdx.z;
    const int kvh  = h >> 2;
    const float scale = 0.08838834764831845f;

    const char* qb  = (const char*)(q16 + ((size_t)(b * H_Q + h) * T_SEQ + qs) * D_HEAD);
    const char* kb_ = (const char*)(k16 + (size_t)(b * H_KV + kvh) * T_SEQ * D_HEAD);
    const char* vb_ = (const char*)(vt16 + (size_t)(b * H_KV + kvh) * D_HEAD * T_SEQ);

    // keys in [qs-512, qs+127]
    const int kb0 = (qs >= WIN) ? qs - WIN : 0;
    const int NB  = ((qs + 64 - kb0) >> 6) + 1;

    auto load_kv = [&](int kb, int st) {
        uint32_t base = sb + AT_Q_B + st * AT_STG_B;
        if (tid < 128) {
            const char* ks = kb_ + (size_t)kb * 256;
            #pragma unroll
            for (int j = 0; j < 8; j++) {
                asm volatile("cp.async.cg.shared.global [%0], [%1], 16;"
                             :: "r"(base + SWZ128(tid * 128 + j * 16)),
                                "l"(ks + tid * 128 + j * 16) : "memory");
            }
        } else {
            int r = tid - 128;
            const char* vs = vb_ + ((size_t)r * T_SEQ + kb) * 2;
            #pragma unroll
            for (int j = 0; j < 8; j++) {
                asm volatile("cp.async.cg.shared.global [%0], [%1], 16;"
                             :: "r"(base + 16384 + SWZ128(r * 128 + j * 16)),
                                "l"(vs + j * 16) : "memory");
            }
        }
    };

    // Q tile: 128 rows x 256B = 256 vrows x 128B
    #pragma unroll
    for (int j = 0; j < 8; j++) {
        asm volatile("cp.async.cg.shared.global [%0], [%1], 16;"
                     :: "r"(sb + SWZ128(tid * 128 + j * 16)),
                        "l"(qb + tid * 128 + j * 16) : "memory");
    }
    load_kv(kb0, 0);
    asm volatile("cp.async.commit_group;" ::: "memory");
    if (NB > 1) {
        load_kv(kb0 + 64, 1);
        asm volatile("cp.async.commit_group;" ::: "memory");
    }

    float O[16][4];
    #pragma unroll
    for (int nt = 0; nt < 16; nt++)
        #pragma unroll
        for (int e = 0; e < 4; e++) O[nt][e] = 0.0f;
    float m0 = -1e30f, m1 = -1e30f, l0 = 0.0f, l1 = 0.0f;

    const int r0g = qs + w * 16 + (lane >> 2);
    const int r1g = r0g + 8;

    for (int i = 0; i < NB; i++) {
        const int kb = kb0 + i * 64;
        const int st = i & 1;
        if (i + 1 < NB) asm volatile("cp.async.wait_group 1;" ::: "memory");
        else            asm volatile("cp.async.wait_group 0;" ::: "memory");
        __syncthreads();

        const uint32_t kbase = sb + AT_Q_B + st * AT_STG_B;
        const uint32_t vbase = kbase + 16384;

        // ---- S = Q K^T ----
        float sreg[8][4];
        #pragma unroll
        for (int t = 0; t < 8; t++)
            #pragma unroll
            for (int e = 0; e < 4; e++) sreg[t][e] = 0.0f;

        #pragma unroll
        for (int ks = 0; ks < 8; ks++) {
            const int khalf = ks >> 2;
            const int kb32  = (ks & 3) * 32;
            uint32_t a[4];
            {
                uint32_t vrow = (uint32_t)(w * 16 + (lane & 15)) * 2 + khalf;
                LDSM_X4(a, sb + SWZ128(vrow * 128 + kb32 + (lane >> 4) * 16));
            }
            #pragma unroll
            for (int g = 0; g < 4; g++) {
                uint32_t bf[4];
                uint32_t vrow = (uint32_t)(g * 16 + (lane & 7) + ((lane >> 4) << 3)) * 2 + khalf;
                LDSM_X4(bf, kbase + SWZ128(vrow * 128 + kb32 + (((lane >> 3) & 1) << 4)));
                MMA16816F(sreg[g * 2],     a, bf[0], bf[1]);
                MMA16816F(sreg[g * 2 + 1], a, bf[2], bf[3]);
            }
        }

        // ---- mask + scale + online softmax ----
        float mx0 = -1e30f, mx1 = -1e30f;
        #pragma unroll
        for (int t = 0; t < 8; t++) {
            int c0 = kb + t * 8 + (lane & 3) * 2;
            int c1 = c0 + 1;
            sreg[t][0] = (c0 <= r0g && r0g - c0 < WIN) ? sreg[t][0] * scale : -1e30f;
            sreg[t][1] = (c1 <= r0g && r0g - c1 < WIN) ? sreg[t][1] * scale : -1e30f;
            sreg[t][2] = (c0 <= r1g && r1g - c0 < WIN) ? sreg[t][2] * scale : -1e30f;
            sreg[t][3] = (c1 <= r1g && r1g - c1 < WIN) ? sreg[t][3] * scale : -1e30f;
            mx0 = fmaxf(mx0, fmaxf(sreg[t][0], sreg[t][1]));
            mx1 = fmaxf(mx1, fmaxf(sreg[t][2], sreg[t][3]));
        }
        mx0 = fmaxf(mx0, __shfl_xor_sync(0xffffffffu, mx0, 1));
        mx0 = fmaxf(mx0, __shfl_xor_sync(0xffffffffu, mx0, 2));
        mx1 = fmaxf(mx1, __shfl_xor_sync(0xffffffffu, mx1, 1));
        mx1 = fmaxf(mx1, __shfl_xor_sync(0xffffffffu, mx1, 2));

        float mn0 = fmaxf(m0, mx0), mn1 = fmaxf(m1, mx1);
        float corr0 = __expf(m0 - mn0), corr1 = __expf(m1 - mn1);
        m0 = mn0; m1 = mn1;

        float sum0 = 0.0f, sum1 = 0.0f;
        #pragma unroll
        for (int t = 0; t < 8; t++) {
            sreg[t][0] = __expf(sreg[t][0] - m0);
            sreg[t][1] = __expf(sreg[t][1] - m0);
            sreg[t][2] = __expf(sreg[t][2] - m1);
            sreg[t][3] = __expf(sreg[t][3] - m1);
            sum0 += sreg[t][0] + sreg[t][1];
            sum1 += sreg[t][2] + sreg[t][3];
        }
        sum0 += __shfl_xor_sync(0xffffffffu, sum0, 1);
        sum0 += __shfl_xor_sync(0xffffffffu, sum0, 2);
        sum1 += __shfl_xor_sync(0xffffffffu, sum1, 1);
        sum1 += __shfl_xor_sync(0xffffffffu, sum1, 2);
        l0 = l0 * corr0 + sum0;
        l1 = l1 * corr1 + sum1;

        #pragma unroll
        for (int nt = 0; nt < 16; nt++) {
            O[nt][0] *= corr0; O[nt][1] *= corr0;
            O[nt][2] *= corr1; O[nt][3] *= corr1;
        }

        // ---- P -> fp16 A-fragments ----
        uint32_t ph[4][4];
        #pragma unroll
        for (int f = 0; f < 4; f++) {
            __half2 p0 = __floats2half2_rn(sreg[2 * f][0],     sreg[2 * f][1]);
            __half2 p1 = __floats2half2_rn(sreg[2 * f][2],     sreg[2 * f][3]);
            __half2 p2 = __floats2half2_rn(sreg[2 * f + 1][0], sreg[2 * f + 1][1]);
            __half2 p3 = __floats2half2_rn(sreg[2 * f + 1][2], sreg[2 * f + 1][3]);
            ph[f][0] = *(uint32_t*)&p0;
            ph[f][1] = *(uint32_t*)&p1;
            ph[f][2] = *(uint32_t*)&p2;
            ph[f][3] = *(uint32_t*)&p3;
        }

        // ---- O += P V ----
        #pragma unroll
        for (int f = 0; f < 4; f++) {
            #pragma unroll
            for (int g = 0; g < 8; g++) {
                uint32_t bf[4];
                uint32_t vrow = (uint32_t)(g * 16 + (lane & 7) + ((lane >> 4) << 3));
                uint32_t off = SWZ128(vrow * 128 + f * 32 + (((lane >> 3) & 1) << 4));
                LDSM_X4(bf, vbase + off);
                MMA16816F(O[2 * g],     ph[f], bf[0], bf[1]);
                MMA16816F(O[2 * g + 1], ph[f], bf[2], bf[3]);
            }
        }

        __syncthreads();
        if (i + 2 < NB) {
            load_kv(kb0 + (i + 2) * 64, st);
        }
        asm volatile("cp.async.commit_group;" ::: "memory");
    }

    float invl0 = 1.0f / l0;
    float invl1 = 1.0f / l1;
    #pragma unroll
    for (int nt = 0; nt < 16; nt++) {
        int col = nt * 8 + (lane & 3) * 2;
        float* d0 = o + ((size_t)(b * T_SEQ + r0g) * H_Q + h) * D_HEAD + col;
        float* d1 = o + ((size_t)(b * T_SEQ + r1g) * H_Q + h) * D_HEAD + col;
        *(float2*)d0 = make_float2(O[nt][0] * invl0, O[nt][1] * invl0);
        *(float2*)d1 = make_float2(O[nt][2] * invl1, O[nt][3] * invl1);
    }
}

// ---------------------------------------------------------------------------
// launch
// ---------------------------------------------------------------------------
extern "C" void kernel_launch(void* const* d_in, const int* in_sizes, int n_in,
                              void* d_out, int out_size)
{
    const float* x  = (const float*)d_in[0];
    const float* Wq = (const float*)d_in[1];
    const float* Wk = (const float*)d_in[2];
    const float* Wv = (const float*)d_in[3];
    const float* Wo = (const float*)d_in[4];
    float* out = (float*)d_out;

    float *q, *k, *v, *att;
    cudaGetSymbolAddress((void**)&q,   g_q);
    cudaGetSymbolAddress((void**)&k,   g_k);
    cudaGetSymbolAddress((void**)&v,   g_v);
    cudaGetSymbolAddress((void**)&att, g_att);

    __half *x16, *wq16, *wk16, *wv16, *wo16, *a16, *q16p, *k16p, *vt16;
    cudaGetSymbolAddress((void**)&x16,  g_x16);
    cudaGetSymbolAddress((void**)&wq16, g_wq16);
    cudaGetSymbolAddress((void**)&wk16, g_wk16);
    cudaGetSymbolAddress((void**)&wv16, g_wv16);
    cudaGetSymbolAddress((void**)&wo16, g_wo16);
    cudaGetSymbolAddress((void**)&a16,  g_a16);
    cudaGetSymbolAddress((void**)&q16p, g_q16p);
    cudaGetSymbolAddress((void**)&k16p, g_k16p);
    cudaGetSymbolAddress((void**)&vt16, g_vt16);

    cudaFuncSetAttribute(qkv_gemm, cudaFuncAttributeMaxDynamicSharedMemorySize, GK_SMEM);
    cudaFuncSetAttribute(h_gemm, cudaFuncAttributeMaxDynamicSharedMemorySize, GK_SMEM);
    cudaFuncSetAttribute(attn_mma_kernel, cudaFuncAttributeMaxDynamicSharedMemorySize, AT_SMEM);

    rope_table_kernel<<<(T_SEQ * 64 + 255) / 256, 256>>>();

    int nx = M_ROWS * E_DIM;
    int nq = H_Q * D_HEAD * E_DIM;
    int nk = H_KV * D_HEAD * E_DIM;
    conv_fp16_kernel<<<(nx / 4 + 255) / 256, 256>>>(x,  x16,  nx);
    conv_fp16_kernel<<<(nq / 4 + 255) / 256, 256>>>(Wq, wq16, nq);
    conv_fp16_kernel<<<(nk / 4 + 255) / 256, 256>>>(Wk, wk16, nk);
    conv_fp16_kernel<<<(nk / 4 + 255) / 256, 256>>>(Wv, wv16, nk);
    conv_fp16_kernel<<<(nq / 4 + 255) / 256, 256>>>(Wo, wo16, nq);

    qkv_gemm<<<dim3(24, 32), 256, GK_SMEM>>>(x16, wq16, wk16, wv16, q, k, v);

    pack_q_kernel<<<(B_SZ * T_SEQ * H_Q  * 64) / 256, 256>>>(q, q16p);
    pack_k_kernel<<<(B_SZ * T_SEQ * H_KV * 64) / 256, 256>>>(k, k16p);
    pack_v_kernel<<<dim3(T_SEQ / 64, D_HEAD / 64, B_SZ * H_KV), 256>>>(v, vt16);

    attn_mma_kernel<<<dim3(T_SEQ / 128, H_Q, B_SZ), 256, AT_SMEM>>>(q16p, k16p, vt16, att);

    conv_fp16_kernel<<<(nx / 4 + 255) / 256, 256>>>(att, a16, nx);
    h_gemm<<<dim3(E_DIM / 128, M_ROWS / 128), 256, GK_SMEM>>>(
        a16, wo16, out, M_ROWS, E_DIM, E_DIM);
}